// round 2
// baseline (speedup 1.0000x reference)
#include <cuda_runtime.h>
#include <cstddef>

// Problem constants (fixed by the reference)
#define BB   2
#define SS   2048
#define HH   2048
#define NHH  16
#define HDD  128
#define MM   (BB * SS)   // 4096 rows

// ---------------------------------------------------------------------------
// Scratch (allocation-free rule: __device__ globals)
// ---------------------------------------------------------------------------
__device__ float g_q[(size_t)BB * NHH * SS * HDD];   // [B,NH,S,HD]
__device__ float g_k[(size_t)BB * NHH * SS * HDD];
__device__ float g_v[(size_t)BB * NHH * SS * HDD];
__device__ float g_att[(size_t)MM * HH];             // [B,S,H] (heads concat)

// ---------------------------------------------------------------------------
// GEMM: C = A @ W^T + bias.  A[M,K] row-major, W[N,K] row-major.
// 128x128 block tile, BK=8, 256 threads, 8x8 micro-tile per thread.
// MODE 0: C row-major [M,N] (used for final output projection)
// MODE 1: C written as [B,NH,S,HD] (head-split layout for Q/K/V)
// ---------------------------------------------------------------------------
template <int MODE>
__global__ __launch_bounds__(256) void gemm_nt(
    const float* __restrict__ A, const float* __restrict__ W,
    const float* __restrict__ bias, float* __restrict__ C,
    int Mdim, int Ndim, int Kdim)
{
    __shared__ float As[8][128];
    __shared__ float Bs[8][128];

    const int tid  = threadIdx.x;
    const int m0   = blockIdx.y * 128;
    const int n0   = blockIdx.x * 128;
    const int tRow = (tid >> 4) * 8;     // 0..120
    const int tCol = (tid & 15) * 8;     // 0..120

    const int lRow = tid >> 1;           // 0..127
    const int lCol = (tid & 1) * 4;      // 0 or 4

    const float* Ap = A + (size_t)(m0 + lRow) * Kdim + lCol;
    const float* Wp = W + (size_t)(n0 + lRow) * Kdim + lCol;

    float acc[8][8];
#pragma unroll
    for (int i = 0; i < 8; i++)
#pragma unroll
        for (int j = 0; j < 8; j++) acc[i][j] = 0.0f;

    for (int k0 = 0; k0 < Kdim; k0 += 8) {
        float4 av = *(const float4*)(Ap + k0);
        float4 wv = *(const float4*)(Wp + k0);
        As[lCol + 0][lRow] = av.x; As[lCol + 1][lRow] = av.y;
        As[lCol + 2][lRow] = av.z; As[lCol + 3][lRow] = av.w;
        Bs[lCol + 0][lRow] = wv.x; Bs[lCol + 1][lRow] = wv.y;
        Bs[lCol + 2][lRow] = wv.z; Bs[lCol + 3][lRow] = wv.w;
        __syncthreads();

#pragma unroll
        for (int kk = 0; kk < 8; kk++) {
            float a[8], b[8];
#pragma unroll
            for (int i = 0; i < 8; i++) a[i] = As[kk][tRow + i];
#pragma unroll
            for (int j = 0; j < 8; j++) b[j] = Bs[kk][tCol + j];
#pragma unroll
            for (int i = 0; i < 8; i++)
#pragma unroll
                for (int j = 0; j < 8; j++)
                    acc[i][j] = fmaf(a[i], b[j], acc[i][j]);
        }
        __syncthreads();
    }

#pragma unroll
    for (int i = 0; i < 8; i++) {
        const int m = m0 + tRow + i;
#pragma unroll
        for (int j = 0; j < 8; j++) {
            const int n = n0 + tCol + j;
            const float c = acc[i][j] + bias[n];
            if (MODE == 0) {
                C[(size_t)m * Ndim + n] = c;
            } else {
                const int b = m / SS, s = m % SS;
                const int h = n >> 7, d = n & 127;   // HD = 128
                C[(((size_t)(b * NHH + h)) * SS + s) * HDD + d] = c;
            }
        }
    }
}

// ---------------------------------------------------------------------------
// Flash attention (fp32, online softmax, causal with block skipping).
// Grid: (S/64, NH, B). Block: 256 threads (16x16).
// Each thread: 4x4 score micro-tile (q rows 4*ty.., k cols 4*tx..),
// then 4x8 output micro-tile (q rows 4*ty.., d cols 8*tx..).
// Row reductions: shuffle over the 16 lanes sharing ty.
// ---------------------------------------------------------------------------
#define QK_STR 129   // Qs/Ks row stride (2-way conflict max)
#define V_STR  132   // Vs row stride (float4-aligned)
#define P_STR  65    // Ps row stride

__global__ __launch_bounds__(256) void flash_attn(
    const float* __restrict__ Q, const float* __restrict__ K,
    const float* __restrict__ V, float* __restrict__ Out)
{
    extern __shared__ float sm[];
    float* Qs = sm;                        // [64][QK_STR]
    float* Ks = Qs + 64 * QK_STR;          // [64][QK_STR]
    float* Vs = Ks + 64 * QK_STR;          // [64][V_STR]
    float* Ps = Vs + 64 * V_STR;           // [64][P_STR]

    const int tid = threadIdx.x;
    const int tx  = tid & 15;
    const int ty  = tid >> 4;
    const int qb  = blockIdx.x;
    const int h   = blockIdx.y;
    const int b   = blockIdx.z;

    const size_t head_base = ((size_t)(b * NHH + h)) * SS * HDD;
    const float* Qg = Q + head_base + (size_t)qb * 64 * HDD;
    const float* Kg = K + head_base;
    const float* Vg = V + head_base;

    const float qscale = 0.08838834764831845f;  // 1/sqrt(128)

    // Load Q tile (scaled)
#pragma unroll
    for (int t = 0; t < 8; t++) {
        const int idx = tid + t * 256;          // float4 index in [64][32]
        const int r = idx >> 5, c = (idx & 31) * 4;
        float4 v = *(const float4*)(Qg + (size_t)r * HDD + c);
        Qs[r * QK_STR + c + 0] = v.x * qscale;
        Qs[r * QK_STR + c + 1] = v.y * qscale;
        Qs[r * QK_STR + c + 2] = v.z * qscale;
        Qs[r * QK_STR + c + 3] = v.w * qscale;
    }

    float m_i[4], l_i[4], o[4][8];
#pragma unroll
    for (int i = 0; i < 4; i++) {
        m_i[i] = -1e30f; l_i[i] = 0.0f;
#pragma unroll
        for (int j = 0; j < 8; j++) o[i][j] = 0.0f;
    }

    const int q0 = qb * 64;

    for (int kb = 0; kb <= qb; kb++) {
        const int k0 = kb * 64;

        // Load K and V tiles
#pragma unroll
        for (int t = 0; t < 8; t++) {
            const int idx = tid + t * 256;
            const int r = idx >> 5, c = (idx & 31) * 4;
            float4 kv = *(const float4*)(Kg + (size_t)(k0 + r) * HDD + c);
            Ks[r * QK_STR + c + 0] = kv.x; Ks[r * QK_STR + c + 1] = kv.y;
            Ks[r * QK_STR + c + 2] = kv.z; Ks[r * QK_STR + c + 3] = kv.w;
            float4 vv = *(const float4*)(Vg + (size_t)(k0 + r) * HDD + c);
            Vs[r * V_STR + c + 0] = vv.x; Vs[r * V_STR + c + 1] = vv.y;
            Vs[r * V_STR + c + 2] = vv.z; Vs[r * V_STR + c + 3] = vv.w;
        }
        __syncthreads();

        // Scores: s[i][j] = q(4ty+i) . k(4tx+j)  (Q pre-scaled)
        float s[4][4];
#pragma unroll
        for (int i = 0; i < 4; i++)
#pragma unroll
            for (int j = 0; j < 4; j++) s[i][j] = 0.0f;

#pragma unroll 8
        for (int d = 0; d < HDD; d++) {
            float a[4], bb[4];
#pragma unroll
            for (int i = 0; i < 4; i++) a[i]  = Qs[(4 * ty + i) * QK_STR + d];
#pragma unroll
            for (int j = 0; j < 4; j++) bb[j] = Ks[(4 * tx + j) * QK_STR + d];
#pragma unroll
            for (int i = 0; i < 4; i++)
#pragma unroll
                for (int j = 0; j < 4; j++)
                    s[i][j] = fmaf(a[i], bb[j], s[i][j]);
        }

        // Causal mask on diagonal block
        if (kb == qb) {
#pragma unroll
            for (int i = 0; i < 4; i++)
#pragma unroll
                for (int j = 0; j < 4; j++)
                    if (k0 + 4 * tx + j > q0 + 4 * ty + i) s[i][j] = -1e30f;
        }

        // Online softmax (per q-row; reduce across the 16 lanes sharing ty)
#pragma unroll
        for (int i = 0; i < 4; i++) {
            float rm = fmaxf(fmaxf(s[i][0], s[i][1]), fmaxf(s[i][2], s[i][3]));
#pragma unroll
            for (int off = 8; off >= 1; off >>= 1)
                rm = fmaxf(rm, __shfl_xor_sync(0xffffffffu, rm, off));
            const float mn   = fmaxf(m_i[i], rm);
            const float corr = __expf(m_i[i] - mn);
            m_i[i] = mn;
            float rs = 0.0f;
#pragma unroll
            for (int j = 0; j < 4; j++) {
                s[i][j] = __expf(s[i][j] - mn);
                rs += s[i][j];
            }
#pragma unroll
            for (int off = 8; off >= 1; off >>= 1)
                rs += __shfl_xor_sync(0xffffffffu, rs, off);
            l_i[i] = l_i[i] * corr + rs;
#pragma unroll
            for (int j = 0; j < 8; j++) o[i][j] *= corr;
#pragma unroll
            for (int j = 0; j < 4; j++)
                Ps[(4 * ty + i) * P_STR + 4 * tx + j] = s[i][j];
        }
        __syncthreads();

        // O += P @ V   (thread owns q rows 4ty.., d cols 8tx..)
#pragma unroll 4
        for (int k = 0; k < 64; k++) {
            float p[4];
#pragma unroll
            for (int i = 0; i < 4; i++) p[i] = Ps[(4 * ty + i) * P_STR + k];
            float4 v0 = *(const float4*)(&Vs[k * V_STR + 8 * tx]);
            float4 v1 = *(const float4*)(&Vs[k * V_STR + 8 * tx + 4]);
#pragma unroll
            for (int i = 0; i < 4; i++) {
                o[i][0] = fmaf(p[i], v0.x, o[i][0]);
                o[i][1] = fmaf(p[i], v0.y, o[i][1]);
                o[i][2] = fmaf(p[i], v0.z, o[i][2]);
                o[i][3] = fmaf(p[i], v0.w, o[i][3]);
                o[i][4] = fmaf(p[i], v1.x, o[i][4]);
                o[i][5] = fmaf(p[i], v1.y, o[i][5]);
                o[i][6] = fmaf(p[i], v1.z, o[i][6]);
                o[i][7] = fmaf(p[i], v1.w, o[i][7]);
            }
        }
        __syncthreads();
    }

    // Epilogue: normalize and write to [B,S,H] (heads concatenated)
#pragma unroll
    for (int i = 0; i < 4; i++) {
        const float inv = 1.0f / l_i[i];
        const int q = q0 + 4 * ty + i;
        float* dst = Out + ((size_t)(b * SS + q)) * HH + h * HDD + 8 * tx;
#pragma unroll
        for (int j = 0; j < 8; j++) dst[j] = o[i][j] * inv;
    }
}

// ---------------------------------------------------------------------------
// Launch
// ---------------------------------------------------------------------------
extern "C" void kernel_launch(void* const* d_in, const int* in_sizes, int n_in,
                              void* d_out, int out_size)
{
    const float* hidden = (const float*)d_in[0];
    // d_in[1] = causal_mask (strict upper-triangular): handled analytically
    const float* Wq = (const float*)d_in[2];
    const float* bq = (const float*)d_in[3];
    const float* Wk = (const float*)d_in[4];
    const float* bk = (const float*)d_in[5];
    const float* Wv = (const float*)d_in[6];
    const float* bv = (const float*)d_in[7];
    const float* Wo = (const float*)d_in[8];
    const float* bo = (const float*)d_in[9];
    float* out = (float*)d_out;

    float *q, *k, *v, *att;
    cudaGetSymbolAddress((void**)&q,   g_q);
    cudaGetSymbolAddress((void**)&k,   g_k);
    cudaGetSymbolAddress((void**)&v,   g_v);
    cudaGetSymbolAddress((void**)&att, g_att);

    const dim3 gthreads(256);
    const dim3 ggrid(HH / 128, MM / 128);

    gemm_nt<1><<<ggrid, gthreads>>>(hidden, Wq, bq, q, MM, HH, HH);
    gemm_nt<1><<<ggrid, gthreads>>>(hidden, Wk, bk, k, MM, HH, HH);
    gemm_nt<1><<<ggrid, gthreads>>>(hidden, Wv, bv, v, MM, HH, HH);

    const int FLASH_SMEM = (64 * QK_STR * 2 + 64 * V_STR + 64 * P_STR) * 4;
    cudaFuncSetAttribute(flash_attn, cudaFuncAttributeMaxDynamicSharedMemorySize,
                         FLASH_SMEM);
    flash_attn<<<dim3(SS / 64, NHH, BB), 256, FLASH_SMEM>>>(q, k, v, att);

    gemm_nt<0><<<ggrid, gthreads>>>(att, Wo, bo, out, MM, HH, HH);
}

// round 3
// speedup vs baseline: 1.6863x; 1.6863x over previous
#include <cuda_runtime.h>
#include <cstdint>
#include <cstddef>

// Problem constants (fixed by the reference)
#define BB   2
#define SS   2048
#define HH   2048
#define NHH  16
#define HDD  128
#define MM   (BB * SS)   // 4096 rows

// ---------------------------------------------------------------------------
// Scratch (allocation-free rule: __device__ globals)
// ---------------------------------------------------------------------------
__device__ float g_q[(size_t)BB * NHH * SS * HDD];   // [B,NH,S,HD]
__device__ float g_k[(size_t)BB * NHH * SS * HDD];
__device__ float g_v[(size_t)BB * NHH * SS * HDD];
__device__ float g_att[(size_t)MM * HH];             // [B,S,H] (heads concat)

// ---------------------------------------------------------------------------
// tf32 helpers
// ---------------------------------------------------------------------------
__device__ __forceinline__ float cvt_tf32(float x) {
    uint32_t u;
    asm("cvt.rna.tf32.f32 %0, %1;" : "=r"(u) : "f"(x));
    return __uint_as_float(u);
}

__device__ __forceinline__ void mma_tf32(float c[4], const uint32_t a[4],
                                         const uint32_t b[2]) {
    asm volatile(
        "mma.sync.aligned.m16n8k8.row.col.f32.tf32.tf32.f32 "
        "{%0,%1,%2,%3}, {%4,%5,%6,%7}, {%8,%9}, {%0,%1,%2,%3};\n"
        : "+f"(c[0]), "+f"(c[1]), "+f"(c[2]), "+f"(c[3])
        : "r"(a[0]), "r"(a[1]), "r"(a[2]), "r"(a[3]), "r"(b[0]), "r"(b[1]));
}

// ---------------------------------------------------------------------------
// tf32 tensor-core GEMM: C = A @ W^T + bias.
// A[M,K] row-major, W[N,K] row-major.
// Block 128x128, BK=32, 256 threads = 8 warps, warp tile 32x64 (2x8 mma tiles).
// Smem rows padded to 36 floats -> all fragment LDS conflict-free.
// MODE 0: C row-major [M,N].  MODE 1: C as [B,NH,S,HD].
// ---------------------------------------------------------------------------
#define GBM 128
#define GBN 128
#define GBK 32
#define GPAD 36

template <int MODE>
__global__ __launch_bounds__(256) void gemm_tf32(
    const float* __restrict__ A, const float* __restrict__ W,
    const float* __restrict__ bias, float* __restrict__ C,
    int Mdim, int Ndim, int Kdim)
{
    __shared__ float As[GBM][GPAD];   // [m][k], cols 0..31 used
    __shared__ float Bs[GBN][GPAD];   // [n][k]

    const int tid  = threadIdx.x;
    const int lane = tid & 31;
    const int warp = tid >> 5;
    const int wm   = (warp >> 1) * 32;   // 0,32,64,96
    const int wn   = (warp & 1) * 64;    // 0,64

    const int m0 = blockIdx.y * GBM;
    const int n0 = blockIdx.x * GBN;

    const float* Ag = A + (size_t)m0 * Kdim;
    const float* Wg = W + (size_t)n0 * Kdim;

    float acc[2][8][4];
#pragma unroll
    for (int i = 0; i < 2; i++)
#pragma unroll
        for (int j = 0; j < 8; j++)
#pragma unroll
            for (int t = 0; t < 4; t++) acc[i][j][t] = 0.0f;

    const int lgr = tid >> 3;          // 0..31 (row within 128 covered in 4 steps)
    const int lgc = (tid & 7) << 2;    // float4 col 0..28

    for (int k0 = 0; k0 < Kdim; k0 += GBK) {
        // Load A and W tiles (128x32 each), cvt.rna -> tf32 bits, store to smem
#pragma unroll
        for (int t = 0; t < 4; t++) {
            const int r = lgr + t * 32;
            float4 av = *(const float4*)(Ag + (size_t)r * Kdim + k0 + lgc);
            av.x = cvt_tf32(av.x); av.y = cvt_tf32(av.y);
            av.z = cvt_tf32(av.z); av.w = cvt_tf32(av.w);
            *(float4*)&As[r][lgc] = av;
            float4 wv = *(const float4*)(Wg + (size_t)r * Kdim + k0 + lgc);
            wv.x = cvt_tf32(wv.x); wv.y = cvt_tf32(wv.y);
            wv.z = cvt_tf32(wv.z); wv.w = cvt_tf32(wv.w);
            *(float4*)&Bs[r][lgc] = wv;
        }
        __syncthreads();

#pragma unroll
        for (int ks = 0; ks < 4; ks++) {
            const int kk = ks * 8 + (lane & 3);
            uint32_t afr[2][4], bfr[8][2];
#pragma unroll
            for (int i = 0; i < 2; i++) {
                const int r = wm + i * 16 + (lane >> 2);
                afr[i][0] = __float_as_uint(As[r][kk]);
                afr[i][1] = __float_as_uint(As[r + 8][kk]);
                afr[i][2] = __float_as_uint(As[r][kk + 4]);
                afr[i][3] = __float_as_uint(As[r + 8][kk + 4]);
            }
#pragma unroll
            for (int j = 0; j < 8; j++) {
                const int n = wn + j * 8 + (lane >> 2);
                bfr[j][0] = __float_as_uint(Bs[n][kk]);
                bfr[j][1] = __float_as_uint(Bs[n][kk + 4]);
            }
#pragma unroll
            for (int i = 0; i < 2; i++)
#pragma unroll
                for (int j = 0; j < 8; j++)
                    mma_tf32(acc[i][j], afr[i], bfr[j]);
        }
        __syncthreads();
    }

    // Epilogue
#pragma unroll
    for (int i = 0; i < 2; i++) {
        const int r = wm + i * 16 + (lane >> 2);
#pragma unroll
        for (int j = 0; j < 8; j++) {
            const int cc = wn + j * 8 + (lane & 3) * 2;
#pragma unroll
            for (int half = 0; half < 2; half++) {
                const int m = m0 + r + half * 8;
                const float v0 = acc[i][j][half * 2 + 0] + bias[n0 + cc];
                const float v1 = acc[i][j][half * 2 + 1] + bias[n0 + cc + 1];
                if (MODE == 0) {
                    float2* dst = (float2*)(C + (size_t)m * Ndim + n0 + cc);
                    *dst = make_float2(v0, v1);
                } else {
                    const int b = m / SS, s = m % SS;
                    const int n = n0 + cc;
                    const int h = n >> 7, d = n & 127;   // HD = 128
                    float2* dst = (float2*)(&g_q[0] +
                        ((C - &g_q[0])) +   // C already points at target buffer
                        0);
                    // direct indexed store (avoid pointer games):
                    float* base = C + (((size_t)(b * NHH + h)) * SS + s) * HDD + d;
                    base[0] = v0; base[1] = v1;
                    (void)dst;
                }
            }
        }
    }
}

// ---------------------------------------------------------------------------
// Flash attention (fp32, online softmax, causal with block skipping).
// Unchanged from round 1 (known-good); tensorized next round.
// ---------------------------------------------------------------------------
#define QK_STR 129
#define V_STR  132
#define P_STR  65

__global__ __launch_bounds__(256) void flash_attn(
    const float* __restrict__ Q, const float* __restrict__ K,
    const float* __restrict__ V, float* __restrict__ Out)
{
    extern __shared__ float sm[];
    float* Qs = sm;
    float* Ks = Qs + 64 * QK_STR;
    float* Vs = Ks + 64 * QK_STR;
    float* Ps = Vs + 64 * V_STR;

    const int tid = threadIdx.x;
    const int tx  = tid & 15;
    const int ty  = tid >> 4;
    const int qb  = blockIdx.x;
    const int h   = blockIdx.y;
    const int b   = blockIdx.z;

    const size_t head_base = ((size_t)(b * NHH + h)) * SS * HDD;
    const float* Qg = Q + head_base + (size_t)qb * 64 * HDD;
    const float* Kg = K + head_base;
    const float* Vg = V + head_base;

    const float qscale = 0.08838834764831845f;  // 1/sqrt(128)

#pragma unroll
    for (int t = 0; t < 8; t++) {
        const int idx = tid + t * 256;
        const int r = idx >> 5, c = (idx & 31) * 4;
        float4 v = *(const float4*)(Qg + (size_t)r * HDD + c);
        Qs[r * QK_STR + c + 0] = v.x * qscale;
        Qs[r * QK_STR + c + 1] = v.y * qscale;
        Qs[r * QK_STR + c + 2] = v.z * qscale;
        Qs[r * QK_STR + c + 3] = v.w * qscale;
    }

    float m_i[4], l_i[4], o[4][8];
#pragma unroll
    for (int i = 0; i < 4; i++) {
        m_i[i] = -1e30f; l_i[i] = 0.0f;
#pragma unroll
        for (int j = 0; j < 8; j++) o[i][j] = 0.0f;
    }

    const int q0 = qb * 64;

    for (int kb = 0; kb <= qb; kb++) {
        const int k0 = kb * 64;

#pragma unroll
        for (int t = 0; t < 8; t++) {
            const int idx = tid + t * 256;
            const int r = idx >> 5, c = (idx & 31) * 4;
            float4 kv = *(const float4*)(Kg + (size_t)(k0 + r) * HDD + c);
            Ks[r * QK_STR + c + 0] = kv.x; Ks[r * QK_STR + c + 1] = kv.y;
            Ks[r * QK_STR + c + 2] = kv.z; Ks[r * QK_STR + c + 3] = kv.w;
            float4 vv = *(const float4*)(Vg + (size_t)(k0 + r) * HDD + c);
            Vs[r * V_STR + c + 0] = vv.x; Vs[r * V_STR + c + 1] = vv.y;
            Vs[r * V_STR + c + 2] = vv.z; Vs[r * V_STR + c + 3] = vv.w;
        }
        __syncthreads();

        float s[4][4];
#pragma unroll
        for (int i = 0; i < 4; i++)
#pragma unroll
            for (int j = 0; j < 4; j++) s[i][j] = 0.0f;

#pragma unroll 8
        for (int d = 0; d < HDD; d++) {
            float a[4], bb[4];
#pragma unroll
            for (int i = 0; i < 4; i++) a[i]  = Qs[(4 * ty + i) * QK_STR + d];
#pragma unroll
            for (int j = 0; j < 4; j++) bb[j] = Ks[(4 * tx + j) * QK_STR + d];
#pragma unroll
            for (int i = 0; i < 4; i++)
#pragma unroll
                for (int j = 0; j < 4; j++)
                    s[i][j] = fmaf(a[i], bb[j], s[i][j]);
        }

        if (kb == qb) {
#pragma unroll
            for (int i = 0; i < 4; i++)
#pragma unroll
                for (int j = 0; j < 4; j++)
                    if (k0 + 4 * tx + j > q0 + 4 * ty + i) s[i][j] = -1e30f;
        }

#pragma unroll
        for (int i = 0; i < 4; i++) {
            float rm = fmaxf(fmaxf(s[i][0], s[i][1]), fmaxf(s[i][2], s[i][3]));
#pragma unroll
            for (int off = 8; off >= 1; off >>= 1)
                rm = fmaxf(rm, __shfl_xor_sync(0xffffffffu, rm, off));
            const float mn   = fmaxf(m_i[i], rm);
            const float corr = __expf(m_i[i] - mn);
            m_i[i] = mn;
            float rs = 0.0f;
#pragma unroll
            for (int j = 0; j < 4; j++) {
                s[i][j] = __expf(s[i][j] - mn);
                rs += s[i][j];
            }
#pragma unroll
            for (int off = 8; off >= 1; off >>= 1)
                rs += __shfl_xor_sync(0xffffffffu, rs, off);
            l_i[i] = l_i[i] * corr + rs;
#pragma unroll
            for (int j = 0; j < 8; j++) o[i][j] *= corr;
#pragma unroll
            for (int j = 0; j < 4; j++)
                Ps[(4 * ty + i) * P_STR + 4 * tx + j] = s[i][j];
        }
        __syncthreads();

#pragma unroll 4
        for (int k = 0; k < 64; k++) {
            float p[4];
#pragma unroll
            for (int i = 0; i < 4; i++) p[i] = Ps[(4 * ty + i) * P_STR + k];
            float4 v0 = *(const float4*)(&Vs[k * V_STR + 8 * tx]);
            float4 v1 = *(const float4*)(&Vs[k * V_STR + 8 * tx + 4]);
#pragma unroll
            for (int i = 0; i < 4; i++) {
                o[i][0] = fmaf(p[i], v0.x, o[i][0]);
                o[i][1] = fmaf(p[i], v0.y, o[i][1]);
                o[i][2] = fmaf(p[i], v0.z, o[i][2]);
                o[i][3] = fmaf(p[i], v0.w, o[i][3]);
                o[i][4] = fmaf(p[i], v1.x, o[i][4]);
                o[i][5] = fmaf(p[i], v1.y, o[i][5]);
                o[i][6] = fmaf(p[i], v1.z, o[i][6]);
                o[i][7] = fmaf(p[i], v1.w, o[i][7]);
            }
        }
        __syncthreads();
    }

#pragma unroll
    for (int i = 0; i < 4; i++) {
        const float inv = 1.0f / l_i[i];
        const int q = q0 + 4 * ty + i;
        float* dst = Out + ((size_t)(b * SS + q)) * HH + h * HDD + 8 * tx;
#pragma unroll
        for (int j = 0; j < 8; j++) dst[j] = o[i][j] * inv;
    }
}

// ---------------------------------------------------------------------------
// Launch
// ---------------------------------------------------------------------------
extern "C" void kernel_launch(void* const* d_in, const int* in_sizes, int n_in,
                              void* d_out, int out_size)
{
    const float* hidden = (const float*)d_in[0];
    // d_in[1] = causal_mask: handled analytically
    const float* Wq = (const float*)d_in[2];
    const float* bq = (const float*)d_in[3];
    const float* Wk = (const float*)d_in[4];
    const float* bk = (const float*)d_in[5];
    const float* Wv = (const float*)d_in[6];
    const float* bv = (const float*)d_in[7];
    const float* Wo = (const float*)d_in[8];
    const float* bo = (const float*)d_in[9];
    float* out = (float*)d_out;

    float *q, *k, *v, *att;
    cudaGetSymbolAddress((void**)&q,   g_q);
    cudaGetSymbolAddress((void**)&k,   g_k);
    cudaGetSymbolAddress((void**)&v,   g_v);
    cudaGetSymbolAddress((void**)&att, g_att);

    const dim3 gthreads(256);
    const dim3 ggrid(HH / GBN, MM / GBM);

    gemm_tf32<1><<<ggrid, gthreads>>>(hidden, Wq, bq, q, MM, HH, HH);
    gemm_tf32<1><<<ggrid, gthreads>>>(hidden, Wk, bk, k, MM, HH, HH);
    gemm_tf32<1><<<ggrid, gthreads>>>(hidden, Wv, bv, v, MM, HH, HH);

    const int FLASH_SMEM = (64 * QK_STR * 2 + 64 * V_STR + 64 * P_STR) * 4;
    cudaFuncSetAttribute(flash_attn, cudaFuncAttributeMaxDynamicSharedMemorySize,
                         FLASH_SMEM);
    flash_attn<<<dim3(SS / 64, NHH, BB), 256, FLASH_SMEM>>>(q, k, v, att);

    gemm_tf32<0><<<ggrid, gthreads>>>(att, Wo, bo, out, MM, HH, HH);
}

// round 4
// speedup vs baseline: 3.4823x; 2.0651x over previous
#include <cuda_runtime.h>
#include <cstdint>
#include <cstddef>

// Problem constants (fixed by the reference)
#define BB   2
#define SS   2048
#define HH   2048
#define NHH  16
#define HDD  128
#define MM   (BB * SS)   // 4096 rows

// ---------------------------------------------------------------------------
// Scratch (allocation-free rule: __device__ globals)
// ---------------------------------------------------------------------------
__device__ float g_q[(size_t)BB * NHH * SS * HDD];   // [B,NH,S,HD]  (tf32-rounded)
__device__ float g_k[(size_t)BB * NHH * SS * HDD];
__device__ float g_v[(size_t)BB * NHH * SS * HDD];
__device__ float g_att[(size_t)MM * HH];             // [B,S,H] (tf32-rounded)
__device__ float g_hidt[(size_t)MM * HH];            // hidden, tf32-rounded
__device__ float g_wt[(size_t)4 * HH * HH];          // Wq,Wk,Wv,Wo tf32-rounded

// ---------------------------------------------------------------------------
// tf32 helpers
// ---------------------------------------------------------------------------
__device__ __forceinline__ float cvt_tf32(float x) {
    uint32_t u;
    asm("cvt.rna.tf32.f32 %0, %1;" : "=r"(u) : "f"(x));
    return __uint_as_float(u);
}

__device__ __forceinline__ void mma_tf32(float c[4], const uint32_t a[4],
                                         const uint32_t b[2]) {
    asm volatile(
        "mma.sync.aligned.m16n8k8.row.col.f32.tf32.tf32.f32 "
        "{%0,%1,%2,%3}, {%4,%5,%6,%7}, {%8,%9}, {%0,%1,%2,%3};\n"
        : "+f"(c[0]), "+f"(c[1]), "+f"(c[2]), "+f"(c[3])
        : "r"(a[0]), "r"(a[1]), "r"(a[2]), "r"(a[3]), "r"(b[0]), "r"(b[1]));
}

__device__ __forceinline__ void cp_async16(void* s, const void* g) {
    uint32_t sa = (uint32_t)__cvta_generic_to_shared(s);
    asm volatile("cp.async.cg.shared.global [%0], [%1], 16;\n"
                 :: "r"(sa), "l"(g));
}

// ---------------------------------------------------------------------------
// Pre-convert: out[i] = tf32_rna(in[i])  (vectorized)
// ---------------------------------------------------------------------------
__global__ __launch_bounds__(256) void cvt_kernel(const float* __restrict__ in,
                                                  float* __restrict__ out, int n4)
{
    int i = blockIdx.x * 256 + threadIdx.x;
    if (i < n4) {
        float4 v = ((const float4*)in)[i];
        v.x = cvt_tf32(v.x); v.y = cvt_tf32(v.y);
        v.z = cvt_tf32(v.z); v.w = cvt_tf32(v.w);
        ((float4*)out)[i] = v;
    }
}

// ---------------------------------------------------------------------------
// tf32 tensor-core GEMM with cp.async double buffering.
// C = A @ W^T + bias. A[M,K], W[N,K] row-major, both pre-rounded to tf32.
// Block 128x128, BK=32, 256 threads = 8 warps, warp tile 32x64.
// MODE 0: C row-major fp32.  MODE 1: C as [B,NH,S,HD], tf32-rounded.
// ---------------------------------------------------------------------------
#define GBM 128
#define GBN 128
#define GBK 32
#define GPAD 36
#define GSTG (2 * GBM * GPAD)   // floats per stage (As + Bs)

template <int MODE>
__global__ __launch_bounds__(256, 2) void gemm_tf32(
    const float* __restrict__ A, const float* __restrict__ W,
    const float* __restrict__ bias, float* __restrict__ C,
    int Mdim, int Ndim, int Kdim)
{
    extern __shared__ float dsm[];

    const int tid  = threadIdx.x;
    const int lane = tid & 31;
    const int warp = tid >> 5;
    const int wm   = (warp >> 1) * 32;
    const int wn   = (warp & 1) * 64;

    const int m0 = blockIdx.y * GBM;
    const int n0 = blockIdx.x * GBN;

    const float* Ag = A + (size_t)m0 * Kdim;
    const float* Wg = W + (size_t)n0 * Kdim;

    const int lgr = tid >> 3;         // 0..31
    const int lgc = (tid & 7) << 2;   // 0,4,..,28

    float acc[2][8][4];
#pragma unroll
    for (int i = 0; i < 2; i++)
#pragma unroll
        for (int j = 0; j < 8; j++)
#pragma unroll
            for (int t = 0; t < 4; t++) acc[i][j][t] = 0.0f;

    // --- async load of one stage ---
    auto load_stage = [&](int stg, int k0) {
        float* As = dsm + stg * GSTG;
        float* Bs = As + GBM * GPAD;
#pragma unroll
        for (int t = 0; t < 4; t++) {
            const int r = lgr + t * 32;
            cp_async16(&As[r * GPAD + lgc], Ag + (size_t)r * Kdim + k0 + lgc);
            cp_async16(&Bs[r * GPAD + lgc], Wg + (size_t)r * Kdim + k0 + lgc);
        }
    };

    const int ntiles = Kdim / GBK;

    load_stage(0, 0);
    asm volatile("cp.async.commit_group;\n");

    for (int kt = 0; kt < ntiles; kt++) {
        if (kt + 1 < ntiles) {
            load_stage((kt + 1) & 1, (kt + 1) * GBK);
            asm volatile("cp.async.commit_group;\n");
            asm volatile("cp.async.wait_group 1;\n");
        } else {
            asm volatile("cp.async.wait_group 0;\n");
        }
        __syncthreads();

        const float* As = dsm + (kt & 1) * GSTG;
        const float* Bs = As + GBM * GPAD;

#pragma unroll
        for (int ks = 0; ks < 4; ks++) {
            const int kk = ks * 8 + (lane & 3);
            uint32_t afr[2][4], bfr[8][2];
#pragma unroll
            for (int i = 0; i < 2; i++) {
                const int r = wm + i * 16 + (lane >> 2);
                afr[i][0] = __float_as_uint(As[r * GPAD + kk]);
                afr[i][1] = __float_as_uint(As[(r + 8) * GPAD + kk]);
                afr[i][2] = __float_as_uint(As[r * GPAD + kk + 4]);
                afr[i][3] = __float_as_uint(As[(r + 8) * GPAD + kk + 4]);
            }
#pragma unroll
            for (int j = 0; j < 8; j++) {
                const int n = wn + j * 8 + (lane >> 2);
                bfr[j][0] = __float_as_uint(Bs[n * GPAD + kk]);
                bfr[j][1] = __float_as_uint(Bs[n * GPAD + kk + 4]);
            }
#pragma unroll
            for (int i = 0; i < 2; i++)
#pragma unroll
                for (int j = 0; j < 8; j++)
                    mma_tf32(acc[i][j], afr[i], bfr[j]);
        }
        __syncthreads();
    }

    // Epilogue
#pragma unroll
    for (int i = 0; i < 2; i++) {
        const int r = wm + i * 16 + (lane >> 2);
#pragma unroll
        for (int j = 0; j < 8; j++) {
            const int cc = wn + j * 8 + (lane & 3) * 2;
#pragma unroll
            for (int half = 0; half < 2; half++) {
                const int m = m0 + r + half * 8;
                float v0 = acc[i][j][half * 2 + 0] + bias[n0 + cc];
                float v1 = acc[i][j][half * 2 + 1] + bias[n0 + cc + 1];
                if (MODE == 0) {
                    float2* dst = (float2*)(C + (size_t)m * Ndim + n0 + cc);
                    *dst = make_float2(v0, v1);
                } else {
                    const int b = m / SS, s = m % SS;
                    const int n = n0 + cc;
                    const int h = n >> 7, d = n & 127;
                    float* base = C + (((size_t)(b * NHH + h)) * SS + s) * HDD + d;
                    base[0] = cvt_tf32(v0);
                    base[1] = cvt_tf32(v1);
                }
            }
        }
    }
}

// ---------------------------------------------------------------------------
// Tensor-core flash attention (tf32 MMA, online softmax, causal block skip).
// Grid: (S/64, NH, B), 256 threads = 8 warps.
// S tile 64x64 (warps 4m x 2n, warp 16x32), O tile 64x128 (warps 4m x 2n,
// warp 16x64). Row stats via smem cross-warp reduction.
// ---------------------------------------------------------------------------
#define AQ_STR 132   // Qs/Ks row stride  -> (4r+k)%32 conflict-free
#define AV_STR 136   // Vs row stride     -> (8k+n)%32 conflict-free
#define AP_STR 68    // Ps row stride     -> (4r+k)%32 conflict-free

__global__ __launch_bounds__(256) void flash_attn_tc(
    const float* __restrict__ Q, const float* __restrict__ K,
    const float* __restrict__ V, float* __restrict__ Out)
{
    extern __shared__ float sm[];
    float* Qs     = sm;                       // [64][AQ_STR]
    float* Ks     = Qs + 64 * AQ_STR;         // [64][AQ_STR]
    float* Vs     = Ks + 64 * AQ_STR;         // [64][AV_STR]
    float* Ps     = Vs + 64 * AV_STR;         // [64][AP_STR]
    float* m_s    = Ps + 64 * AP_STR;         // [64]
    float* l_s    = m_s + 64;                 // [64]
    float* corr_s = l_s + 64;                 // [64]
    float* red    = corr_s + 64;              // [128] partial max / partial sum

    const int tid  = threadIdx.x;
    const int lane = tid & 31;
    const int warp = tid >> 5;
    const int wmS  = (warp >> 1) * 16;        // S warp row (also O warp row)
    const int wnS  = (warp & 1) * 32;         // S warp col
    const int wnO  = (warp & 1) * 64;         // O warp col
    const int wpn  = warp & 1;                // n-half id

    const int qb = blockIdx.x;
    const int h  = blockIdx.y;
    const int b  = blockIdx.z;
    const int q0 = qb * 64;

    const size_t head_base = ((size_t)(b * NHH + h)) * SS * HDD;
    const float* Qg = Q + head_base + (size_t)q0 * HDD;
    const float* Kg = K + head_base;
    const float* Vg = V + head_base;

    const float qscale = 0.08838834764831845f;  // 1/sqrt(128)

    // init stats
    if (tid < 64) { m_s[tid] = -1e30f; l_s[tid] = 0.0f; }

    // load Q tile (raw tf32-rounded values; scale applied post-MMA)
#pragma unroll
    for (int t = 0; t < 8; t++) {
        const int idx = tid + t * 256;
        const int r = idx >> 5, c = (idx & 31) * 4;
        float4 v = *(const float4*)(Qg + (size_t)r * HDD + c);
        *(float4*)&Qs[r * AQ_STR + c] = v;
    }

    float o[8][4];
#pragma unroll
    for (int j = 0; j < 8; j++)
#pragma unroll
        for (int t = 0; t < 4; t++) o[j][t] = 0.0f;

    const int r0S = wmS + (lane >> 2);   // S/O row for c0,c1
    const int r1S = r0S + 8;             // row for c2,c3

    for (int kb = 0; kb <= qb; kb++) {
        const int k0 = kb * 64;

        // load K,V tiles
#pragma unroll
        for (int t = 0; t < 8; t++) {
            const int idx = tid + t * 256;
            const int r = idx >> 5, c = (idx & 31) * 4;
            float4 kv = *(const float4*)(Kg + (size_t)(k0 + r) * HDD + c);
            *(float4*)&Ks[r * AQ_STR + c] = kv;
            float4 vv = *(const float4*)(Vg + (size_t)(k0 + r) * HDD + c);
            *(float4*)&Vs[r * AV_STR + c] = vv;
        }
        __syncthreads();

        // ---- S = Q @ K^T (64x64x128) ----
        float s[4][4];
#pragma unroll
        for (int j = 0; j < 4; j++)
#pragma unroll
            for (int t = 0; t < 4; t++) s[j][t] = 0.0f;

#pragma unroll
        for (int ks = 0; ks < 16; ks++) {
            const int kk = ks * 8 + (lane & 3);
            uint32_t a[4];
            a[0] = __float_as_uint(Qs[r0S * AQ_STR + kk]);
            a[1] = __float_as_uint(Qs[r1S * AQ_STR + kk]);
            a[2] = __float_as_uint(Qs[r0S * AQ_STR + kk + 4]);
            a[3] = __float_as_uint(Qs[r1S * AQ_STR + kk + 4]);
#pragma unroll
            for (int j = 0; j < 4; j++) {
                const int n = wnS + j * 8 + (lane >> 2);
                uint32_t bb[2];
                bb[0] = __float_as_uint(Ks[n * AQ_STR + kk]);
                bb[1] = __float_as_uint(Ks[n * AQ_STR + kk + 4]);
                mma_tf32(s[j], a, bb);
            }
        }

        // scale + causal mask
#pragma unroll
        for (int j = 0; j < 4; j++)
#pragma unroll
            for (int t = 0; t < 4; t++) s[j][t] *= qscale;

        if (kb == qb) {
#pragma unroll
            for (int j = 0; j < 4; j++) {
                const int cg = k0 + wnS + j * 8 + (lane & 3) * 2;
#pragma unroll
                for (int t = 0; t < 4; t++) {
                    const int rg = q0 + ((t < 2) ? r0S : r1S);
                    if (cg + (t & 1) > rg) s[j][t] = -1e30f;
                }
            }
        }

        // partial row max (this warp's 32 cols)
        float mx0 = -1e30f, mx1 = -1e30f;
#pragma unroll
        for (int j = 0; j < 4; j++) {
            mx0 = fmaxf(mx0, fmaxf(s[j][0], s[j][1]));
            mx1 = fmaxf(mx1, fmaxf(s[j][2], s[j][3]));
        }
        mx0 = fmaxf(mx0, __shfl_xor_sync(0xffffffffu, mx0, 1));
        mx0 = fmaxf(mx0, __shfl_xor_sync(0xffffffffu, mx0, 2));
        mx1 = fmaxf(mx1, __shfl_xor_sync(0xffffffffu, mx1, 1));
        mx1 = fmaxf(mx1, __shfl_xor_sync(0xffffffffu, mx1, 2));
        if ((lane & 3) == 0) {
            red[r0S + 64 * wpn] = mx0;
            red[r1S + 64 * wpn] = mx1;
        }
        __syncthreads();

        // global row stats
        if (tid < 64) {
            const float m_old = m_s[tid];
            const float m_new = fmaxf(m_old, fmaxf(red[tid], red[tid + 64]));
            m_s[tid]    = m_new;
            corr_s[tid] = __expf(m_old - m_new);
        }
        __syncthreads();

        // exp, P -> smem (tf32-rounded), partial row sums
        {
            const float mn0 = m_s[r0S];
            const float mn1 = m_s[r1S];
            float sum0 = 0.0f, sum1 = 0.0f;
#pragma unroll
            for (int j = 0; j < 4; j++) {
                const int col = wnS + j * 8 + (lane & 3) * 2;
                float p0 = __expf(s[j][0] - mn0);
                float p1 = __expf(s[j][1] - mn0);
                float p2 = __expf(s[j][2] - mn1);
                float p3 = __expf(s[j][3] - mn1);
                sum0 += p0 + p1; sum1 += p2 + p3;
                Ps[r0S * AP_STR + col]     = cvt_tf32(p0);
                Ps[r0S * AP_STR + col + 1] = cvt_tf32(p1);
                Ps[r1S * AP_STR + col]     = cvt_tf32(p2);
                Ps[r1S * AP_STR + col + 1] = cvt_tf32(p3);
            }
            sum0 += __shfl_xor_sync(0xffffffffu, sum0, 1);
            sum0 += __shfl_xor_sync(0xffffffffu, sum0, 2);
            sum1 += __shfl_xor_sync(0xffffffffu, sum1, 1);
            sum1 += __shfl_xor_sync(0xffffffffu, sum1, 2);
            if ((lane & 3) == 0) {
                red[r0S + 64 * wpn] = sum0;
                red[r1S + 64 * wpn] = sum1;
            }
        }
        __syncthreads();

        if (tid < 64)
            l_s[tid] = l_s[tid] * corr_s[tid] + red[tid] + red[tid + 64];

        // ---- O = corr*O + P @ V  (64x128x64) ----
        {
            const float c0 = corr_s[r0S];
            const float c1 = corr_s[r1S];
#pragma unroll
            for (int j = 0; j < 8; j++) {
                o[j][0] *= c0; o[j][1] *= c0;
                o[j][2] *= c1; o[j][3] *= c1;
            }
#pragma unroll
            for (int ks = 0; ks < 8; ks++) {
                const int kk = ks * 8 + (lane & 3);
                uint32_t a[4];
                a[0] = __float_as_uint(Ps[r0S * AP_STR + kk]);
                a[1] = __float_as_uint(Ps[r1S * AP_STR + kk]);
                a[2] = __float_as_uint(Ps[r0S * AP_STR + kk + 4]);
                a[3] = __float_as_uint(Ps[r1S * AP_STR + kk + 4]);
#pragma unroll
                for (int j = 0; j < 8; j++) {
                    const int n = wnO + j * 8 + (lane >> 2);
                    uint32_t bb[2];
                    bb[0] = __float_as_uint(Vs[kk * AV_STR + n]);
                    bb[1] = __float_as_uint(Vs[(kk + 4) * AV_STR + n]);
                    mma_tf32(o[j], a, bb);
                }
            }
        }
        __syncthreads();   // protect Ks/Vs/Ps before next iteration
    }

    // epilogue: normalize, write att [B,S,H] tf32-rounded for final GEMM
    {
        const float inv0 = 1.0f / l_s[r0S];
        const float inv1 = 1.0f / l_s[r1S];
        float* dst0 = Out + ((size_t)(b * SS + q0 + r0S)) * HH + h * HDD;
        float* dst1 = Out + ((size_t)(b * SS + q0 + r1S)) * HH + h * HDD;
#pragma unroll
        for (int j = 0; j < 8; j++) {
            const int col = wnO + j * 8 + (lane & 3) * 2;
            dst0[col]     = cvt_tf32(o[j][0] * inv0);
            dst0[col + 1] = cvt_tf32(o[j][1] * inv0);
            dst1[col]     = cvt_tf32(o[j][2] * inv1);
            dst1[col + 1] = cvt_tf32(o[j][3] * inv1);
        }
    }
}

// ---------------------------------------------------------------------------
// Launch
// ---------------------------------------------------------------------------
extern "C" void kernel_launch(void* const* d_in, const int* in_sizes, int n_in,
                              void* d_out, int out_size)
{
    const float* hidden = (const float*)d_in[0];
    // d_in[1] = causal_mask: handled analytically
    const float* Wq = (const float*)d_in[2];
    const float* bq = (const float*)d_in[3];
    const float* Wk = (const float*)d_in[4];
    const float* bk = (const float*)d_in[5];
    const float* Wv = (const float*)d_in[6];
    const float* bv = (const float*)d_in[7];
    const float* Wo = (const float*)d_in[8];
    const float* bo = (const float*)d_in[9];
    float* out = (float*)d_out;

    float *q, *k, *v, *att, *hidt, *wt;
    cudaGetSymbolAddress((void**)&q,    g_q);
    cudaGetSymbolAddress((void**)&k,    g_k);
    cudaGetSymbolAddress((void**)&v,    g_v);
    cudaGetSymbolAddress((void**)&att,  g_att);
    cudaGetSymbolAddress((void**)&hidt, g_hidt);
    cudaGetSymbolAddress((void**)&wt,   g_wt);

    // Pre-round inputs to tf32 so GEMMs can cp.async raw bits
    const int HN4 = MM * HH / 4;       // hidden float4 count
    const int WN4 = HH * HH / 4;       // weight float4 count
    cvt_kernel<<<HN4 / 256, 256>>>(hidden, hidt, HN4);
    cvt_kernel<<<WN4 / 256, 256>>>(Wq, wt + 0 * (size_t)HH * HH, WN4);
    cvt_kernel<<<WN4 / 256, 256>>>(Wk, wt + 1 * (size_t)HH * HH, WN4);
    cvt_kernel<<<WN4 / 256, 256>>>(Wv, wt + 2 * (size_t)HH * HH, WN4);
    cvt_kernel<<<WN4 / 256, 256>>>(Wo, wt + 3 * (size_t)HH * HH, WN4);

    const int GEMM_SMEM = 2 * GSTG * (int)sizeof(float);  // 73728 B
    cudaFuncSetAttribute(gemm_tf32<0>, cudaFuncAttributeMaxDynamicSharedMemorySize,
                         GEMM_SMEM);
    cudaFuncSetAttribute(gemm_tf32<1>, cudaFuncAttributeMaxDynamicSharedMemorySize,
                         GEMM_SMEM);

    const dim3 gthreads(256);
    const dim3 ggrid(HH / GBN, MM / GBM);

    gemm_tf32<1><<<ggrid, gthreads, GEMM_SMEM>>>(hidt, wt + 0 * (size_t)HH * HH, bq, q, MM, HH, HH);
    gemm_tf32<1><<<ggrid, gthreads, GEMM_SMEM>>>(hidt, wt + 1 * (size_t)HH * HH, bk, k, MM, HH, HH);
    gemm_tf32<1><<<ggrid, gthreads, GEMM_SMEM>>>(hidt, wt + 2 * (size_t)HH * HH, bv, v, MM, HH, HH);

    const int FLASH_SMEM =
        (64 * AQ_STR * 2 + 64 * AV_STR + 64 * AP_STR + 64 * 3 + 128) * (int)sizeof(float);
    cudaFuncSetAttribute(flash_attn_tc, cudaFuncAttributeMaxDynamicSharedMemorySize,
                         FLASH_SMEM);
    flash_attn_tc<<<dim3(SS / 64, NHH, BB), 256, FLASH_SMEM>>>(q, k, v, att);

    gemm_tf32<0><<<ggrid, gthreads, GEMM_SMEM>>>(att, wt + 3 * (size_t)HH * HH, bo, out, MM, HH, HH);
}

// round 6
// speedup vs baseline: 5.4282x; 1.5588x over previous
#include <cuda_runtime.h>
#include <cuda_fp16.h>
#include <cstdint>
#include <cstddef>

// Problem constants (fixed by the reference)
#define BB   2
#define SS   2048
#define HH   2048
#define NHH  16
#define HDD  128
#define MM   (BB * SS)   // 4096 rows

// ---------------------------------------------------------------------------
// Scratch (allocation-free rule: __device__ globals)
// ---------------------------------------------------------------------------
__device__ __half g_q[(size_t)BB * NHH * SS * HDD];   // [B,NH,S,HD]
__device__ __half g_k[(size_t)BB * NHH * SS * HDD];
__device__ __half g_v[(size_t)BB * NHH * SS * HDD];
__device__ __half g_att[(size_t)MM * HH];             // [B,S,H]
__device__ __half g_hidt[(size_t)MM * HH];            // hidden, fp16
__device__ __half g_wt[(size_t)4 * HH * HH];          // Wq,Wk,Wv,Wo fp16

// ---------------------------------------------------------------------------
// Helpers
// ---------------------------------------------------------------------------
__device__ __forceinline__ void mma_f16(float c[4], const uint32_t a[4],
                                        const uint32_t b[2]) {
    asm volatile(
        "mma.sync.aligned.m16n8k16.row.col.f32.f16.f16.f32 "
        "{%0,%1,%2,%3}, {%4,%5,%6,%7}, {%8,%9}, {%0,%1,%2,%3};\n"
        : "+f"(c[0]), "+f"(c[1]), "+f"(c[2]), "+f"(c[3])
        : "r"(a[0]), "r"(a[1]), "r"(a[2]), "r"(a[3]), "r"(b[0]), "r"(b[1]));
}

__device__ __forceinline__ void cp_async16(uint32_t s, const void* g) {
    asm volatile("cp.async.cg.shared.global [%0], [%1], 16;\n" :: "r"(s), "l"(g));
}

__device__ __forceinline__ uint32_t smem_u32(const void* p) {
    return (uint32_t)__cvta_generic_to_shared(p);
}

__device__ __forceinline__ void ldmatrix_x4_trans(
    uint32_t& r0, uint32_t& r1, uint32_t& r2, uint32_t& r3, uint32_t saddr) {
    asm volatile(
        "ldmatrix.sync.aligned.m8n8.x4.trans.shared.b16 {%0,%1,%2,%3}, [%4];"
        : "=r"(r0), "=r"(r1), "=r"(r2), "=r"(r3) : "r"(saddr));
}

// ---------------------------------------------------------------------------
// Pre-convert: fp32 -> fp16 (rn), vectorized
// ---------------------------------------------------------------------------
__global__ __launch_bounds__(256) void cvt_f2h(const float* __restrict__ in,
                                               __half* __restrict__ out, int n4)
{
    int i = blockIdx.x * 256 + threadIdx.x;
    if (i < n4) {
        float4 v = ((const float4*)in)[i];
        __half2* o = (__half2*)(out + (size_t)i * 4);
        o[0] = __floats2half2_rn(v.x, v.y);
        o[1] = __floats2half2_rn(v.z, v.w);
    }
}

// ---------------------------------------------------------------------------
// fp16 tensor-core GEMM: C = A @ W^T + bias.
// A[M,K], W[N,K] row-major fp16. Block 128x128, BK=64 halves, 2-stage cp.async.
// 256 threads = 8 warps, warp tile 32x64 (2 x 8 mma tiles of m16n8k16).
// Smem rows padded to 72 halves (36 words) -> all fragment LDS conflict-free.
// MODE 0: Cf row-major fp32.  MODE 1: Ch as [B,NH,S,HD] fp16.
// ---------------------------------------------------------------------------
#define GROW_B   144                 // bytes per smem row (72 halves)
#define GROW_W   36                  // words per smem row
#define GTILE_B  (128 * GROW_B)      // 18432 bytes per tile
#define GSTG_B   (2 * GTILE_B)       // A + B per stage
#define GEMM_SMEM (512 + 2 * GSTG_B) // bias + 2 stages = 74240

template <int MODE>
__global__ __launch_bounds__(256, 2) void gemm_f16(
    const __half* __restrict__ A, const __half* __restrict__ W,
    const float* __restrict__ bias, float* __restrict__ Cf,
    __half* __restrict__ Ch, int Mdim, int Ndim, int Kdim)
{
    extern __shared__ char smc[];
    const uint32_t smem_base = smem_u32(smc);
    float* bias_s = (float*)smc;

    const int tid  = threadIdx.x;
    const int lane = tid & 31;
    const int warp = tid >> 5;
    const int wm   = (warp >> 1) * 32;   // 0,32,64,96
    const int wn   = (warp & 1) * 64;    // 0,64

    const int m0 = blockIdx.y * 128;
    const int n0 = blockIdx.x * 128;

    if (tid < 128) bias_s[tid] = bias[n0 + tid];

    const int lrow = tid >> 1;           // 0..127
    const int lch0 = (tid & 1) * 4;      // 16B chunk base 0 or 4

    const __half* Ag = A + (size_t)(m0 + lrow) * Kdim;
    const __half* Wg = W + (size_t)(n0 + lrow) * Kdim;

    auto load_tile = [&](int stage, int k0 /*halves*/) {
        const uint32_t sa = smem_base + 512 + stage * GSTG_B + lrow * GROW_B;
        const uint32_t sb = sa + GTILE_B;
#pragma unroll
        for (int c = 0; c < 4; c++) {
            const int ch = lch0 + c;                 // 0..7
            cp_async16(sa + ch * 16, Ag + k0 + ch * 8);
            cp_async16(sb + ch * 16, Wg + k0 + ch * 8);
        }
        asm volatile("cp.async.commit_group;\n");
    };

    float acc[2][8][4];
#pragma unroll
    for (int i = 0; i < 2; i++)
#pragma unroll
        for (int j = 0; j < 8; j++)
#pragma unroll
            for (int t = 0; t < 4; t++) acc[i][j][t] = 0.0f;

    const int ntiles = Kdim / 64;
    load_tile(0, 0);

    for (int kt = 0; kt < ntiles; kt++) {
        if (kt + 1 < ntiles) {
            load_tile((kt + 1) & 1, (kt + 1) * 64);
            asm volatile("cp.async.wait_group 1;\n");
        } else {
            asm volatile("cp.async.wait_group 0;\n");
        }
        __syncthreads();

        const uint32_t* As = (const uint32_t*)(smc + 512 + (kt & 1) * GSTG_B);
        const uint32_t* Bs = As + GTILE_B / 4;

#pragma unroll
        for (int ks = 0; ks < 4; ks++) {
            const int kk = ks * 8 + (lane & 3);
            uint32_t afr[2][4], bfr[8][2];
#pragma unroll
            for (int i = 0; i < 2; i++) {
                const int r = wm + i * 16 + (lane >> 2);
                afr[i][0] = As[r * GROW_W + kk];
                afr[i][1] = As[(r + 8) * GROW_W + kk];
                afr[i][2] = As[r * GROW_W + kk + 4];
                afr[i][3] = As[(r + 8) * GROW_W + kk + 4];
            }
#pragma unroll
            for (int j = 0; j < 8; j++) {
                const int n = wn + j * 8 + (lane >> 2);
                bfr[j][0] = Bs[n * GROW_W + kk];
                bfr[j][1] = Bs[n * GROW_W + kk + 4];
            }
#pragma unroll
            for (int i = 0; i < 2; i++)
#pragma unroll
                for (int j = 0; j < 8; j++)
                    mma_f16(acc[i][j], afr[i], bfr[j]);
        }
        __syncthreads();
    }

    // Epilogue
#pragma unroll
    for (int i = 0; i < 2; i++) {
        const int r = wm + i * 16 + (lane >> 2);
#pragma unroll
        for (int j = 0; j < 8; j++) {
            const int cc = wn + j * 8 + (lane & 3) * 2;
#pragma unroll
            for (int hh = 0; hh < 2; hh++) {
                const int m = m0 + r + hh * 8;
                const float v0 = acc[i][j][hh * 2 + 0] + bias_s[cc];
                const float v1 = acc[i][j][hh * 2 + 1] + bias_s[cc + 1];
                if (MODE == 0) {
                    *(float2*)(Cf + (size_t)m * Ndim + n0 + cc) = make_float2(v0, v1);
                } else {
                    const int b = m / SS, s = m % SS;
                    const int n = n0 + cc;
                    const int h = n >> 7, d = n & 127;   // HD = 128
                    __half2* dst = (__half2*)(Ch +
                        (((size_t)(b * NHH + h)) * SS + s) * HDD + d);
                    *dst = __floats2half2_rn(v0, v1);
                }
            }
        }
    }
}

// ---------------------------------------------------------------------------
// fp16 tensor-core flash attention (online softmax, causal block skip).
// Grid: (S/64, NH, B), 256 threads = 8 warps.
// S tile 64x64 (warps 4m x 2n, warp 16x32), O tile 64x128 (warp 16x64).
// Q/K/V smem rows padded to 136 halves (68 words); P rows to 72 halves.
// P.V uses ldmatrix.x4.trans on row-major V for B fragments.
// ---------------------------------------------------------------------------
#define FQ_ROW_H 136                  // halves per Q/K/V smem row
#define FQ_ROW_W 68
#define FQ_ROW_B 272
#define FP_ROW_H 72                   // halves per P smem row
#define FP_ROW_W 36
#define OFF_QS   0
#define OFF_KS   17408
#define OFF_VS   34816
#define OFF_PS   52224                // 64*72*2 = 9216
#define OFF_MS   61440
#define OFF_LS   61696
#define OFF_CS   61952
#define OFF_RED  62208
#define FLASH_SMEM 62720

__global__ __launch_bounds__(256) void flash_attn_f16(
    const __half* __restrict__ Q, const __half* __restrict__ K,
    const __half* __restrict__ V, __half* __restrict__ Out)
{
    extern __shared__ char smc[];
    const uint32_t smem_base = smem_u32(smc);
    __half* Qs = (__half*)(smc + OFF_QS);
    __half* Ks = (__half*)(smc + OFF_KS);
    __half* Vs = (__half*)(smc + OFF_VS);
    __half* Ps = (__half*)(smc + OFF_PS);
    float* m_s    = (float*)(smc + OFF_MS);
    float* l_s    = (float*)(smc + OFF_LS);
    float* corr_s = (float*)(smc + OFF_CS);
    float* red    = (float*)(smc + OFF_RED);
    const uint32_t* Qs32 = (const uint32_t*)Qs;
    const uint32_t* Ks32 = (const uint32_t*)Ks;
    const uint32_t* Ps32 = (const uint32_t*)Ps;

    const int tid  = threadIdx.x;
    const int lane = tid & 31;
    const int warp = tid >> 5;
    const int wmS  = (warp >> 1) * 16;
    const int wnS  = (warp & 1) * 32;
    const int wnO  = (warp & 1) * 64;
    const int wpn  = warp & 1;

    const int qb = blockIdx.x;
    const int h  = blockIdx.y;
    const int b  = blockIdx.z;
    const int q0 = qb * 64;

    const size_t head_base = ((size_t)(b * NHH + h)) * SS * HDD;
    const __half* Qg = Q + head_base + (size_t)q0 * HDD;
    const __half* Kg = K + head_base;
    const __half* Vg = V + head_base;

    const float qscale = 0.08838834764831845f;  // 1/sqrt(128)

    if (tid < 64) { m_s[tid] = -1e30f; l_s[tid] = 0.0f; }

    // Load Q tile: 64 rows x 128 halves = 1024 16B chunks
#pragma unroll
    for (int t = 0; t < 4; t++) {
        const int c = tid + t * 256;
        const int r = c >> 4, col = (c & 15) * 8;
        *(uint4*)&Qs[r * FQ_ROW_H + col] = *(const uint4*)(Qg + (size_t)r * HDD + col);
    }

    float o[8][4];
#pragma unroll
    for (int j = 0; j < 8; j++)
#pragma unroll
        for (int t = 0; t < 4; t++) o[j][t] = 0.0f;

    const int r0S = wmS + (lane >> 2);
    const int r1S = r0S + 8;

    // ldmatrix per-lane address pieces for V (rows = seq k, cols = head dim)
    const uint32_t v_lane_byte = (uint32_t)((lane & 15) * FQ_ROW_B + 16 * (lane >> 4));

    for (int kb = 0; kb <= qb; kb++) {
        const int k0 = kb * 64;

#pragma unroll
        for (int t = 0; t < 4; t++) {
            const int c = tid + t * 256;
            const int r = c >> 4, col = (c & 15) * 8;
            *(uint4*)&Ks[r * FQ_ROW_H + col] =
                *(const uint4*)(Kg + (size_t)(k0 + r) * HDD + col);
            *(uint4*)&Vs[r * FQ_ROW_H + col] =
                *(const uint4*)(Vg + (size_t)(k0 + r) * HDD + col);
        }
        __syncthreads();

        // ---- S = Q @ K^T (64x64x128), fp16 m16n8k16 ----
        float s[4][4];
#pragma unroll
        for (int j = 0; j < 4; j++)
#pragma unroll
            for (int t = 0; t < 4; t++) s[j][t] = 0.0f;

#pragma unroll
        for (int ks = 0; ks < 8; ks++) {
            const int kk = ks * 8 + (lane & 3);
            uint32_t a[4];
            a[0] = Qs32[r0S * FQ_ROW_W + kk];
            a[1] = Qs32[r1S * FQ_ROW_W + kk];
            a[2] = Qs32[r0S * FQ_ROW_W + kk + 4];
            a[3] = Qs32[r1S * FQ_ROW_W + kk + 4];
#pragma unroll
            for (int j = 0; j < 4; j++) {
                const int n = wnS + j * 8 + (lane >> 2);
                uint32_t bb[2];
                bb[0] = Ks32[n * FQ_ROW_W + kk];
                bb[1] = Ks32[n * FQ_ROW_W + kk + 4];
                mma_f16(s[j], a, bb);
            }
        }

#pragma unroll
        for (int j = 0; j < 4; j++)
#pragma unroll
            for (int t = 0; t < 4; t++) s[j][t] *= qscale;

        if (kb == qb) {
#pragma unroll
            for (int j = 0; j < 4; j++) {
                const int cg = k0 + wnS + j * 8 + (lane & 3) * 2;
#pragma unroll
                for (int t = 0; t < 4; t++) {
                    const int rg = q0 + ((t < 2) ? r0S : r1S);
                    if (cg + (t & 1) > rg) s[j][t] = -1e30f;
                }
            }
        }

        // partial row max across this warp's 32 cols
        float mx0 = -1e30f, mx1 = -1e30f;
#pragma unroll
        for (int j = 0; j < 4; j++) {
            mx0 = fmaxf(mx0, fmaxf(s[j][0], s[j][1]));
            mx1 = fmaxf(mx1, fmaxf(s[j][2], s[j][3]));
        }
        mx0 = fmaxf(mx0, __shfl_xor_sync(0xffffffffu, mx0, 1));
        mx0 = fmaxf(mx0, __shfl_xor_sync(0xffffffffu, mx0, 2));
        mx1 = fmaxf(mx1, __shfl_xor_sync(0xffffffffu, mx1, 1));
        mx1 = fmaxf(mx1, __shfl_xor_sync(0xffffffffu, mx1, 2));
        if ((lane & 3) == 0) {
            red[r0S + 64 * wpn] = mx0;
            red[r1S + 64 * wpn] = mx1;
        }
        __syncthreads();

        if (tid < 64) {
            const float m_old = m_s[tid];
            const float m_new = fmaxf(m_old, fmaxf(red[tid], red[tid + 64]));
            m_s[tid]    = m_new;
            corr_s[tid] = __expf(m_old - m_new);
        }
        __syncthreads();

        // exp, P -> smem fp16, partial row sums
        {
            const float mn0 = m_s[r0S];
            const float mn1 = m_s[r1S];
            float sum0 = 0.0f, sum1 = 0.0f;
#pragma unroll
            for (int j = 0; j < 4; j++) {
                const int colw = (wnS >> 1) + j * 4 + (lane & 3);  // half2 word idx
                float p0 = __expf(s[j][0] - mn0);
                float p1 = __expf(s[j][1] - mn0);
                float p2 = __expf(s[j][2] - mn1);
                float p3 = __expf(s[j][3] - mn1);
                sum0 += p0 + p1; sum1 += p2 + p3;
                ((__half2*)Ps)[r0S * FP_ROW_W + colw] = __floats2half2_rn(p0, p1);
                ((__half2*)Ps)[r1S * FP_ROW_W + colw] = __floats2half2_rn(p2, p3);
            }
            sum0 += __shfl_xor_sync(0xffffffffu, sum0, 1);
            sum0 += __shfl_xor_sync(0xffffffffu, sum0, 2);
            sum1 += __shfl_xor_sync(0xffffffffu, sum1, 1);
            sum1 += __shfl_xor_sync(0xffffffffu, sum1, 2);
            if ((lane & 3) == 0) {
                red[r0S + 64 * wpn] = sum0;
                red[r1S + 64 * wpn] = sum1;
            }
        }
        __syncthreads();

        if (tid < 64)
            l_s[tid] = l_s[tid] * corr_s[tid] + red[tid] + red[tid + 64];

        // ---- O = corr*O + P @ V  (64x128x64), V via ldmatrix.trans ----
        {
            const float c0 = corr_s[r0S];
            const float c1 = corr_s[r1S];
#pragma unroll
            for (int j = 0; j < 8; j++) {
                o[j][0] *= c0; o[j][1] *= c0;
                o[j][2] *= c1; o[j][3] *= c1;
            }
#pragma unroll
            for (int ks = 0; ks < 4; ks++) {
                const int kk = ks * 8 + (lane & 3);
                uint32_t a[4];
                a[0] = Ps32[r0S * FP_ROW_W + kk];
                a[1] = Ps32[r1S * FP_ROW_W + kk];
                a[2] = Ps32[r0S * FP_ROW_W + kk + 4];
                a[3] = Ps32[r1S * FP_ROW_W + kk + 4];
#pragma unroll
                for (int jj = 0; jj < 4; jj++) {
                    uint32_t b0, b1, b2, b3;
                    const uint32_t vaddr = smem_base + OFF_VS +
                        (uint32_t)(ks * 16) * FQ_ROW_B +
                        (uint32_t)((wnO + jj * 16) * 2) + v_lane_byte;
                    ldmatrix_x4_trans(b0, b1, b2, b3, vaddr);
                    uint32_t bb0[2] = {b0, b1};
                    uint32_t bb1[2] = {b2, b3};
                    mma_f16(o[jj * 2 + 0], a, bb0);
                    mma_f16(o[jj * 2 + 1], a, bb1);
                }
            }
        }
        __syncthreads();
    }

    // epilogue: normalize, write att [B,S,H] fp16
    {
        const float inv0 = 1.0f / l_s[r0S];
        const float inv1 = 1.0f / l_s[r1S];
        __half* dst0 = Out + ((size_t)(b * SS + q0 + r0S)) * HH + h * HDD;
        __half* dst1 = Out + ((size_t)(b * SS + q0 + r1S)) * HH + h * HDD;
#pragma unroll
        for (int j = 0; j < 8; j++) {
            const int col = wnO + j * 8 + (lane & 3) * 2;
            *(__half2*)(dst0 + col) = __floats2half2_rn(o[j][0] * inv0, o[j][1] * inv0);
            *(__half2*)(dst1 + col) = __floats2half2_rn(o[j][2] * inv1, o[j][3] * inv1);
        }
    }
}

// ---------------------------------------------------------------------------
// Launch
// ---------------------------------------------------------------------------
extern "C" void kernel_launch(void* const* d_in, const int* in_sizes, int n_in,
                              void* d_out, int out_size)
{
    const float* hidden = (const float*)d_in[0];
    // d_in[1] = causal_mask: handled analytically
    const float* Wq = (const float*)d_in[2];
    const float* bq = (const float*)d_in[3];
    const float* Wk = (const float*)d_in[4];
    const float* bk = (const float*)d_in[5];
    const float* Wv = (const float*)d_in[6];
    const float* bv = (const float*)d_in[7];
    const float* Wo = (const float*)d_in[8];
    const float* bo = (const float*)d_in[9];
    float* out = (float*)d_out;

    __half *q, *k, *v, *att, *hidt, *wt;
    cudaGetSymbolAddress((void**)&q,    g_q);
    cudaGetSymbolAddress((void**)&k,    g_k);
    cudaGetSymbolAddress((void**)&v,    g_v);
    cudaGetSymbolAddress((void**)&att,  g_att);
    cudaGetSymbolAddress((void**)&hidt, g_hidt);
    cudaGetSymbolAddress((void**)&wt,   g_wt);

    // Convert inputs to fp16
    const int HN4 = MM * HH / 4;
    const int WN4 = HH * HH / 4;
    cvt_f2h<<<HN4 / 256, 256>>>(hidden, hidt, HN4);
    cvt_f2h<<<WN4 / 256, 256>>>(Wq, wt + 0 * (size_t)HH * HH, WN4);
    cvt_f2h<<<WN4 / 256, 256>>>(Wk, wt + 1 * (size_t)HH * HH, WN4);
    cvt_f2h<<<WN4 / 256, 256>>>(Wv, wt + 2 * (size_t)HH * HH, WN4);
    cvt_f2h<<<WN4 / 256, 256>>>(Wo, wt + 3 * (size_t)HH * HH, WN4);

    cudaFuncSetAttribute(gemm_f16<0>, cudaFuncAttributeMaxDynamicSharedMemorySize,
                         GEMM_SMEM);
    cudaFuncSetAttribute(gemm_f16<1>, cudaFuncAttributeMaxDynamicSharedMemorySize,
                         GEMM_SMEM);
    cudaFuncSetAttribute(flash_attn_f16, cudaFuncAttributeMaxDynamicSharedMemorySize,
                         FLASH_SMEM);

    const dim3 gthreads(256);
    const dim3 ggrid(HH / 128, MM / 128);

    gemm_f16<1><<<ggrid, gthreads, GEMM_SMEM>>>(hidt, wt + 0 * (size_t)HH * HH,
                                                bq, nullptr, q, MM, HH, HH);
    gemm_f16<1><<<ggrid, gthreads, GEMM_SMEM>>>(hidt, wt + 1 * (size_t)HH * HH,
                                                bk, nullptr, k, MM, HH, HH);
    gemm_f16<1><<<ggrid, gthreads, GEMM_SMEM>>>(hidt, wt + 2 * (size_t)HH * HH,
                                                bv, nullptr, v, MM, HH, HH);

    flash_attn_f16<<<dim3(SS / 64, NHH, BB), 256, FLASH_SMEM>>>(q, k, v, att);

    gemm_f16<0><<<ggrid, gthreads, GEMM_SMEM>>>(att, wt + 3 * (size_t)HH * HH,
                                                bo, out, nullptr, MM, HH, HH);
}

// round 12
// speedup vs baseline: 5.7910x; 1.0668x over previous
#include <cuda_runtime.h>
#include <cuda_fp16.h>
#include <cstdint>
#include <cstddef>

// Problem constants (fixed by the reference)
#define BB   2
#define SS   2048
#define HH   2048
#define NHH  16
#define HDD  128
#define MM   (BB * SS)   // 4096 rows

// ---------------------------------------------------------------------------
// Scratch (allocation-free rule: __device__ globals)
// ---------------------------------------------------------------------------
__device__ __half g_q[(size_t)BB * NHH * SS * HDD];   // [B,NH,S,HD]
__device__ __half g_k[(size_t)BB * NHH * SS * HDD];
__device__ __half g_v[(size_t)BB * NHH * SS * HDD];
__device__ __half g_att[(size_t)MM * HH];             // [B,S,H]
__device__ __half g_hidt[(size_t)MM * HH];            // hidden, fp16
__device__ __half g_wt[(size_t)3 * HH * HH];          // Wq,Wk,Wv concat (fp16)
__device__ __half g_wo[(size_t)HH * HH];              // Wo fp16

// ---------------------------------------------------------------------------
// Helpers
// ---------------------------------------------------------------------------
__device__ __forceinline__ void mma_f16(float c[4], const uint32_t a[4],
                                        const uint32_t b[2]) {
    asm volatile(
        "mma.sync.aligned.m16n8k16.row.col.f32.f16.f16.f32 "
        "{%0,%1,%2,%3}, {%4,%5,%6,%7}, {%8,%9}, {%0,%1,%2,%3};\n"
        : "+f"(c[0]), "+f"(c[1]), "+f"(c[2]), "+f"(c[3])
        : "r"(a[0]), "r"(a[1]), "r"(a[2]), "r"(a[3]), "r"(b[0]), "r"(b[1]));
}

__device__ __forceinline__ void cp_async16(uint32_t s, const void* g) {
    asm volatile("cp.async.cg.shared.global [%0], [%1], 16;\n" :: "r"(s), "l"(g));
}

__device__ __forceinline__ uint32_t smem_u32(const void* p) {
    return (uint32_t)__cvta_generic_to_shared(p);
}

__device__ __forceinline__ void ldmatrix_x4_trans(
    uint32_t& r0, uint32_t& r1, uint32_t& r2, uint32_t& r3, uint32_t saddr) {
    asm volatile(
        "ldmatrix.sync.aligned.m8n8.x4.trans.shared.b16 {%0,%1,%2,%3}, [%4];"
        : "=r"(r0), "=r"(r1), "=r"(r2), "=r"(r3) : "r"(saddr));
}

// ---------------------------------------------------------------------------
// Pre-convert: fp32 -> fp16 (rn), vectorized
// ---------------------------------------------------------------------------
__global__ __launch_bounds__(256) void cvt_f2h(const float* __restrict__ in,
                                               __half* __restrict__ out, int n4)
{
    int i = blockIdx.x * 256 + threadIdx.x;
    if (i < n4) {
        float4 v = ((const float4*)in)[i];
        __half2* o = (__half2*)(out + (size_t)i * 4);
        o[0] = __floats2half2_rn(v.x, v.y);
        o[1] = __floats2half2_rn(v.z, v.w);
    }
}

// ---------------------------------------------------------------------------
// fp16 tensor-core GEMM: C = A @ W^T + bias.  (proven R5 body)
// Block 128x128, BK=64 halves, 2-stage cp.async. 8 warps, warp tile 32x64.
// Smem rows padded to 72 halves (36 words) -> fragment LDS conflict-free.
// MODE 0: single fp32 row-major output (final projection).
// MODE 2: fused QKV — W has 3*HH concat rows; block column selects q/k/v
//         target + bias, written as [B,NH,S,HD] fp16.
// ---------------------------------------------------------------------------
#define GROW_B   144                 // bytes per smem row (72 halves)
#define GROW_W   36                  // words per smem row
#define GTILE_B  (128 * GROW_B)      // 18432 bytes per tile
#define GSTG_B   (2 * GTILE_B)       // A + B per stage
#define GEMM_SMEM (512 + 2 * GSTG_B) // bias + 2 stages = 74240

template <int MODE>
__global__ __launch_bounds__(256, 2) void gemm_f16(
    const __half* __restrict__ A, const __half* __restrict__ W,
    const float* __restrict__ b0, const float* __restrict__ b1,
    const float* __restrict__ b2, float* __restrict__ Cf,
    __half* __restrict__ o0, __half* __restrict__ o1, __half* __restrict__ o2,
    int Kdim)
{
    extern __shared__ char smc[];
    const uint32_t smem_base = smem_u32(smc);
    float* bias_s = (float*)smc;

    const int tid  = threadIdx.x;
    const int lane = tid & 31;
    const int warp = tid >> 5;
    const int wm   = (warp >> 1) * 32;   // 0,32,64,96
    const int wn   = (warp & 1) * 64;    // 0,64

    const int m0  = blockIdx.y * 128;
    const int n0g = blockIdx.x * 128;    // column across (possibly concat) W

    int nloc;
    int sel;
    const float* bias;
    if (MODE == 2) {
        sel  = n0g >> 11;                // 0:q 1:k 2:v
        nloc = n0g & 2047;
        bias = (sel == 0) ? b0 : (sel == 1) ? b1 : b2;
    } else {
        sel = 0; nloc = n0g; bias = b0;
    }
    if (tid < 128) bias_s[tid] = bias[nloc + tid];

    const int lrow = tid >> 1;           // 0..127
    const int lch0 = (tid & 1) * 4;      // 16B chunk base 0 or 4

    const __half* Ag = A + (size_t)(m0 + lrow) * Kdim;
    const __half* Wg = W + (size_t)(n0g + lrow) * Kdim;

    auto load_tile = [&](int stage, int k0 /*halves*/) {
        const uint32_t sa = smem_base + 512 + stage * GSTG_B + lrow * GROW_B;
        const uint32_t sb = sa + GTILE_B;
#pragma unroll
        for (int c = 0; c < 4; c++) {
            const int ch = lch0 + c;                 // 0..7
            cp_async16(sa + ch * 16, Ag + k0 + ch * 8);
            cp_async16(sb + ch * 16, Wg + k0 + ch * 8);
        }
        asm volatile("cp.async.commit_group;\n");
    };

    float acc[2][8][4];
#pragma unroll
    for (int i = 0; i < 2; i++)
#pragma unroll
        for (int j = 0; j < 8; j++)
#pragma unroll
            for (int t = 0; t < 4; t++) acc[i][j][t] = 0.0f;

    const int ntiles = Kdim / 64;
    load_tile(0, 0);

    for (int kt = 0; kt < ntiles; kt++) {
        if (kt + 1 < ntiles) {
            load_tile((kt + 1) & 1, (kt + 1) * 64);
            asm volatile("cp.async.wait_group 1;\n");
        } else {
            asm volatile("cp.async.wait_group 0;\n");
        }
        __syncthreads();

        const uint32_t* As = (const uint32_t*)(smc + 512 + (kt & 1) * GSTG_B);
        const uint32_t* Bs = As + GTILE_B / 4;

#pragma unroll
        for (int ks = 0; ks < 4; ks++) {
            const int kk = ks * 8 + (lane & 3);
            uint32_t afr[2][4], bfr[8][2];
#pragma unroll
            for (int i = 0; i < 2; i++) {
                const int r = wm + i * 16 + (lane >> 2);
                afr[i][0] = As[r * GROW_W + kk];
                afr[i][1] = As[(r + 8) * GROW_W + kk];
                afr[i][2] = As[r * GROW_W + kk + 4];
                afr[i][3] = As[(r + 8) * GROW_W + kk + 4];
            }
#pragma unroll
            for (int j = 0; j < 8; j++) {
                const int n = wn + j * 8 + (lane >> 2);
                bfr[j][0] = Bs[n * GROW_W + kk];
                bfr[j][1] = Bs[n * GROW_W + kk + 4];
            }
#pragma unroll
            for (int i = 0; i < 2; i++)
#pragma unroll
                for (int j = 0; j < 8; j++)
                    mma_f16(acc[i][j], afr[i], bfr[j]);
        }
        __syncthreads();
    }

    // Epilogue
    __half* Ch = (MODE == 2) ? ((sel == 0) ? o0 : (sel == 1) ? o1 : o2) : (__half*)0;
#pragma unroll
    for (int i = 0; i < 2; i++) {
        const int r = wm + i * 16 + (lane >> 2);
#pragma unroll
        for (int j = 0; j < 8; j++) {
            const int cc = wn + j * 8 + (lane & 3) * 2;
#pragma unroll
            for (int hh = 0; hh < 2; hh++) {
                const int m = m0 + r + hh * 8;
                const float v0 = acc[i][j][hh * 2 + 0] + bias_s[cc];
                const float v1 = acc[i][j][hh * 2 + 1] + bias_s[cc + 1];
                if (MODE == 0) {
                    *(float2*)(Cf + (size_t)m * HH + nloc + cc) = make_float2(v0, v1);
                } else {
                    const int b = m / SS, s = m % SS;
                    const int n = nloc + cc;
                    const int h = n >> 7, d = n & 127;   // HD = 128
                    __half2* dst = (__half2*)(Ch +
                        (((size_t)(b * NHH + h)) * SS + s) * HDD + d);
                    *dst = __floats2half2_rn(v0, v1);
                }
            }
        }
    }
}

// ---------------------------------------------------------------------------
// fp16 tensor-core flash attention (proven R5 kernel, unchanged).
// Grid: (S/64, NH, B), 256 threads = 8 warps.
// S tile 64x64 (warps 4m x 2n, warp 16x32), O tile 64x128 (warp 16x64).
// Q/K/V smem rows padded to 136 halves (68 words); P rows to 72 halves.
// P.V uses ldmatrix.x4.trans on row-major V for B fragments.
// ---------------------------------------------------------------------------
#define FQ_ROW_H 136                  // halves per Q/K/V smem row
#define FQ_ROW_W 68
#define FQ_ROW_B 272
#define FP_ROW_H 72                   // halves per P smem row
#define FP_ROW_W 36
#define OFF_QS   0
#define OFF_KS   17408
#define OFF_VS   34816
#define OFF_PS   52224                // 64*72*2 = 9216
#define OFF_MS   61440
#define OFF_LS   61696
#define OFF_CS   61952
#define OFF_RED  62208
#define FLASH_SMEM 62720

__global__ __launch_bounds__(256) void flash_attn_f16(
    const __half* __restrict__ Q, const __half* __restrict__ K,
    const __half* __restrict__ V, __half* __restrict__ Out)
{
    extern __shared__ char smc[];
    const uint32_t smem_base = smem_u32(smc);
    __half* Qs = (__half*)(smc + OFF_QS);
    __half* Ks = (__half*)(smc + OFF_KS);
    __half* Vs = (__half*)(smc + OFF_VS);
    __half* Ps = (__half*)(smc + OFF_PS);
    float* m_s    = (float*)(smc + OFF_MS);
    float* l_s    = (float*)(smc + OFF_LS);
    float* corr_s = (float*)(smc + OFF_CS);
    float* red    = (float*)(smc + OFF_RED);
    const uint32_t* Qs32 = (const uint32_t*)Qs;
    const uint32_t* Ks32 = (const uint32_t*)Ks;
    const uint32_t* Ps32 = (const uint32_t*)Ps;

    const int tid  = threadIdx.x;
    const int lane = tid & 31;
    const int warp = tid >> 5;
    const int wmS  = (warp >> 1) * 16;
    const int wnS  = (warp & 1) * 32;
    const int wnO  = (warp & 1) * 64;
    const int wpn  = warp & 1;

    const int qb = blockIdx.x;
    const int h  = blockIdx.y;
    const int b  = blockIdx.z;
    const int q0 = qb * 64;

    const size_t head_base = ((size_t)(b * NHH + h)) * SS * HDD;
    const __half* Qg = Q + head_base + (size_t)q0 * HDD;
    const __half* Kg = K + head_base;
    const __half* Vg = V + head_base;

    const float qscale = 0.08838834764831845f;  // 1/sqrt(128)

    if (tid < 64) { m_s[tid] = -1e30f; l_s[tid] = 0.0f; }

    // Load Q tile: 64 rows x 128 halves = 1024 16B chunks
#pragma unroll
    for (int t = 0; t < 4; t++) {
        const int c = tid + t * 256;
        const int r = c >> 4, col = (c & 15) * 8;
        *(uint4*)&Qs[r * FQ_ROW_H + col] = *(const uint4*)(Qg + (size_t)r * HDD + col);
    }

    float o[8][4];
#pragma unroll
    for (int j = 0; j < 8; j++)
#pragma unroll
        for (int t = 0; t < 4; t++) o[j][t] = 0.0f;

    const int r0S = wmS + (lane >> 2);
    const int r1S = r0S + 8;

    // ldmatrix per-lane address pieces for V (rows = seq k, cols = head dim)
    const uint32_t v_lane_byte = (uint32_t)((lane & 15) * FQ_ROW_B + 16 * (lane >> 4));

    for (int kb = 0; kb <= qb; kb++) {
        const int k0 = kb * 64;

#pragma unroll
        for (int t = 0; t < 4; t++) {
            const int c = tid + t * 256;
            const int r = c >> 4, col = (c & 15) * 8;
            *(uint4*)&Ks[r * FQ_ROW_H + col] =
                *(const uint4*)(Kg + (size_t)(k0 + r) * HDD + col);
            *(uint4*)&Vs[r * FQ_ROW_H + col] =
                *(const uint4*)(Vg + (size_t)(k0 + r) * HDD + col);
        }
        __syncthreads();

        // ---- S = Q @ K^T (64x64x128), fp16 m16n8k16 ----
        float s[4][4];
#pragma unroll
        for (int j = 0; j < 4; j++)
#pragma unroll
            for (int t = 0; t < 4; t++) s[j][t] = 0.0f;

#pragma unroll
        for (int ks = 0; ks < 8; ks++) {
            const int kk = ks * 8 + (lane & 3);
            uint32_t a[4];
            a[0] = Qs32[r0S * FQ_ROW_W + kk];
            a[1] = Qs32[r1S * FQ_ROW_W + kk];
            a[2] = Qs32[r0S * FQ_ROW_W + kk + 4];
            a[3] = Qs32[r1S * FQ_ROW_W + kk + 4];
#pragma unroll
            for (int j = 0; j < 4; j++) {
                const int n = wnS + j * 8 + (lane >> 2);
                uint32_t bb[2];
                bb[0] = Ks32[n * FQ_ROW_W + kk];
                bb[1] = Ks32[n * FQ_ROW_W + kk + 4];
                mma_f16(s[j], a, bb);
            }
        }

#pragma unroll
        for (int j = 0; j < 4; j++)
#pragma unroll
            for (int t = 0; t < 4; t++) s[j][t] *= qscale;

        if (kb == qb) {
#pragma unroll
            for (int j = 0; j < 4; j++) {
                const int cg = k0 + wnS + j * 8 + (lane & 3) * 2;
#pragma unroll
                for (int t = 0; t < 4; t++) {
                    const int rg = q0 + ((t < 2) ? r0S : r1S);
                    if (cg + (t & 1) > rg) s[j][t] = -1e30f;
                }
            }
        }

        // partial row max across this warp's 32 cols
        float mx0 = -1e30f, mx1 = -1e30f;
#pragma unroll
        for (int j = 0; j < 4; j++) {
            mx0 = fmaxf(mx0, fmaxf(s[j][0], s[j][1]));
            mx1 = fmaxf(mx1, fmaxf(s[j][2], s[j][3]));
        }
        mx0 = fmaxf(mx0, __shfl_xor_sync(0xffffffffu, mx0, 1));
        mx0 = fmaxf(mx0, __shfl_xor_sync(0xffffffffu, mx0, 2));
        mx1 = fmaxf(mx1, __shfl_xor_sync(0xffffffffu, mx1, 1));
        mx1 = fmaxf(mx1, __shfl_xor_sync(0xffffffffu, mx1, 2));
        if ((lane & 3) == 0) {
            red[r0S + 64 * wpn] = mx0;
            red[r1S + 64 * wpn] = mx1;
        }
        __syncthreads();

        if (tid < 64) {
            const float m_old = m_s[tid];
            const float m_new = fmaxf(m_old, fmaxf(red[tid], red[tid + 64]));
            m_s[tid]    = m_new;
            corr_s[tid] = __expf(m_old - m_new);
        }
        __syncthreads();

        // exp, P -> smem fp16, partial row sums
        {
            const float mn0 = m_s[r0S];
            const float mn1 = m_s[r1S];
            float sum0 = 0.0f, sum1 = 0.0f;
#pragma unroll
            for (int j = 0; j < 4; j++) {
                const int colw = (wnS >> 1) + j * 4 + (lane & 3);  // half2 word idx
                float p0 = __expf(s[j][0] - mn0);
                float p1 = __expf(s[j][1] - mn0);
                float p2 = __expf(s[j][2] - mn1);
                float p3 = __expf(s[j][3] - mn1);
                sum0 += p0 + p1; sum1 += p2 + p3;
                ((__half2*)Ps)[r0S * FP_ROW_W + colw] = __floats2half2_rn(p0, p1);
                ((__half2*)Ps)[r1S * FP_ROW_W + colw] = __floats2half2_rn(p2, p3);
            }
            sum0 += __shfl_xor_sync(0xffffffffu, sum0, 1);
            sum0 += __shfl_xor_sync(0xffffffffu, sum0, 2);
            sum1 += __shfl_xor_sync(0xffffffffu, sum1, 1);
            sum1 += __shfl_xor_sync(0xffffffffu, sum1, 2);
            if ((lane & 3) == 0) {
                red[r0S + 64 * wpn] = sum0;
                red[r1S + 64 * wpn] = sum1;
            }
        }
        __syncthreads();

        if (tid < 64)
            l_s[tid] = l_s[tid] * corr_s[tid] + red[tid] + red[tid + 64];

        // ---- O = corr*O + P @ V  (64x128x64), V via ldmatrix.trans ----
        {
            const float c0 = corr_s[r0S];
            const float c1 = corr_s[r1S];
#pragma unroll
            for (int j = 0; j < 8; j++) {
                o[j][0] *= c0; o[j][1] *= c0;
                o[j][2] *= c1; o[j][3] *= c1;
            }
#pragma unroll
            for (int ks = 0; ks < 4; ks++) {
                const int kk = ks * 8 + (lane & 3);
                uint32_t a[4];
                a[0] = Ps32[r0S * FP_ROW_W + kk];
                a[1] = Ps32[r1S * FP_ROW_W + kk];
                a[2] = Ps32[r0S * FP_ROW_W + kk + 4];
                a[3] = Ps32[r1S * FP_ROW_W + kk + 4];
#pragma unroll
                for (int jj = 0; jj < 4; jj++) {
                    uint32_t b0, b1, b2, b3;
                    const uint32_t vaddr = smem_base + OFF_VS +
                        (uint32_t)(ks * 16) * FQ_ROW_B +
                        (uint32_t)((wnO + jj * 16) * 2) + v_lane_byte;
                    ldmatrix_x4_trans(b0, b1, b2, b3, vaddr);
                    uint32_t bb0[2] = {b0, b1};
                    uint32_t bb1[2] = {b2, b3};
                    mma_f16(o[jj * 2 + 0], a, bb0);
                    mma_f16(o[jj * 2 + 1], a, bb1);
                }
            }
        }
        __syncthreads();
    }

    // epilogue: normalize, write att [B,S,H] fp16
    {
        const float inv0 = 1.0f / l_s[r0S];
        const float inv1 = 1.0f / l_s[r1S];
        __half* dst0 = Out + ((size_t)(b * SS + q0 + r0S)) * HH + h * HDD;
        __half* dst1 = Out + ((size_t)(b * SS + q0 + r1S)) * HH + h * HDD;
#pragma unroll
        for (int j = 0; j < 8; j++) {
            const int col = wnO + j * 8 + (lane & 3) * 2;
            *(__half2*)(dst0 + col) = __floats2half2_rn(o[j][0] * inv0, o[j][1] * inv0);
            *(__half2*)(dst1 + col) = __floats2half2_rn(o[j][2] * inv1, o[j][3] * inv1);
        }
    }
}

// ---------------------------------------------------------------------------
// Launch
// ---------------------------------------------------------------------------
extern "C" void kernel_launch(void* const* d_in, const int* in_sizes, int n_in,
                              void* d_out, int out_size)
{
    const float* hidden = (const float*)d_in[0];
    // d_in[1] = causal_mask: handled analytically
    const float* Wq = (const float*)d_in[2];
    const float* bq = (const float*)d_in[3];
    const float* Wk = (const float*)d_in[4];
    const float* bk = (const float*)d_in[5];
    const float* Wv = (const float*)d_in[6];
    const float* bv = (const float*)d_in[7];
    const float* Wo = (const float*)d_in[8];
    const float* bo = (const float*)d_in[9];
    float* out = (float*)d_out;

    __half *q, *k, *v, *att, *hidt, *wt, *wo;
    cudaGetSymbolAddress((void**)&q,    g_q);
    cudaGetSymbolAddress((void**)&k,    g_k);
    cudaGetSymbolAddress((void**)&v,    g_v);
    cudaGetSymbolAddress((void**)&att,  g_att);
    cudaGetSymbolAddress((void**)&hidt, g_hidt);
    cudaGetSymbolAddress((void**)&wt,   g_wt);
    cudaGetSymbolAddress((void**)&wo,   g_wo);

    // Convert inputs to fp16 (QKV weights into concat layout for fused GEMM)
    const int HN4 = MM * HH / 4;
    const int WN4 = HH * HH / 4;
    cvt_f2h<<<HN4 / 256, 256>>>(hidden, hidt, HN4);
    cvt_f2h<<<WN4 / 256, 256>>>(Wq, wt + 0 * (size_t)HH * HH, WN4);
    cvt_f2h<<<WN4 / 256, 256>>>(Wk, wt + 1 * (size_t)HH * HH, WN4);
    cvt_f2h<<<WN4 / 256, 256>>>(Wv, wt + 2 * (size_t)HH * HH, WN4);
    cvt_f2h<<<WN4 / 256, 256>>>(Wo, wo, WN4);

    cudaFuncSetAttribute(gemm_f16<0>, cudaFuncAttributeMaxDynamicSharedMemorySize,
                         GEMM_SMEM);
    cudaFuncSetAttribute(gemm_f16<2>, cudaFuncAttributeMaxDynamicSharedMemorySize,
                         GEMM_SMEM);
    cudaFuncSetAttribute(flash_attn_f16, cudaFuncAttributeMaxDynamicSharedMemorySize,
                         FLASH_SMEM);

    // Fused QKV projection: N = 6144 over concatenated weights (1536 CTAs)
    gemm_f16<2><<<dim3(48, MM / 128), 256, GEMM_SMEM>>>(
        hidt, wt, bq, bk, bv, nullptr, q, k, v, HH);

    // Flash attention (proven 64-row kernel)
    flash_attn_f16<<<dim3(SS / 64, NHH, BB), 256, FLASH_SMEM>>>(q, k, v, att);

    // Output projection (fp32 result)
    gemm_f16<0><<<dim3(16, MM / 128), 256, GEMM_SMEM>>>(
        att, wo, bo, nullptr, nullptr, out, nullptr, nullptr, nullptr, HH);
}

// round 14
// speedup vs baseline: 6.0942x; 1.0524x over previous
#include <cuda_runtime.h>
#include <cuda_fp16.h>
#include <cstdint>
#include <cstddef>

// Problem constants (fixed by the reference)
#define BB   2
#define SS   2048
#define HH   2048
#define NHH  16
#define HDD  128
#define MM   (BB * SS)   // 4096 rows

// ---------------------------------------------------------------------------
// Scratch (allocation-free rule: __device__ globals)
// ---------------------------------------------------------------------------
__device__ __half g_q[(size_t)BB * NHH * SS * HDD];   // [B,NH,S,HD]
__device__ __half g_k[(size_t)BB * NHH * SS * HDD];
__device__ __half g_v[(size_t)BB * NHH * SS * HDD];
__device__ __half g_att[(size_t)MM * HH];             // [B,S,H]
__device__ __half g_hidt[(size_t)MM * HH];            // hidden, fp16
__device__ __half g_wt[(size_t)3 * HH * HH];          // Wq,Wk,Wv concat (fp16)
__device__ __half g_wo[(size_t)HH * HH];              // Wo fp16

// ---------------------------------------------------------------------------
// Helpers
// ---------------------------------------------------------------------------
__device__ __forceinline__ void mma_f16(float c[4], const uint32_t a[4],
                                        const uint32_t b[2]) {
    asm volatile(
        "mma.sync.aligned.m16n8k16.row.col.f32.f16.f16.f32 "
        "{%0,%1,%2,%3}, {%4,%5,%6,%7}, {%8,%9}, {%0,%1,%2,%3};\n"
        : "+f"(c[0]), "+f"(c[1]), "+f"(c[2]), "+f"(c[3])
        : "r"(a[0]), "r"(a[1]), "r"(a[2]), "r"(a[3]), "r"(b[0]), "r"(b[1]));
}

__device__ __forceinline__ void cp_async16(uint32_t s, const void* g) {
    asm volatile("cp.async.cg.shared.global [%0], [%1], 16;\n" :: "r"(s), "l"(g));
}

__device__ __forceinline__ uint32_t smem_u32(const void* p) {
    return (uint32_t)__cvta_generic_to_shared(p);
}

__device__ __forceinline__ void ldmatrix_x4_trans(
    uint32_t& r0, uint32_t& r1, uint32_t& r2, uint32_t& r3, uint32_t saddr) {
    asm volatile(
        "ldmatrix.sync.aligned.m8n8.x4.trans.shared.b16 {%0,%1,%2,%3}, [%4];"
        : "=r"(r0), "=r"(r1), "=r"(r2), "=r"(r3) : "r"(saddr));
}

// ---------------------------------------------------------------------------
// Pre-convert: fp32 -> fp16 (rn), vectorized
// ---------------------------------------------------------------------------
__global__ __launch_bounds__(256) void cvt_f2h(const float* __restrict__ in,
                                               __half* __restrict__ out, int n4)
{
    int i = blockIdx.x * 256 + threadIdx.x;
    if (i < n4) {
        float4 v = ((const float4*)in)[i];
        __half2* o = (__half2*)(out + (size_t)i * 4);
        o[0] = __floats2half2_rn(v.x, v.y);
        o[1] = __floats2half2_rn(v.z, v.w);
    }
}

// ---------------------------------------------------------------------------
// fp16 tensor-core GEMM: C = A @ W^T + bias.  (proven compute body)
// Block 128x128, BK=64 halves, THREE-stage cp.async pipeline, ONE sync/tile.
// 8 warps, warp tile 32x64. Smem rows padded to 72 halves -> conflict-free.
// MODE 0: single fp32 row-major output (final projection).
// MODE 2: fused QKV — W has 3*HH concat rows; block column selects q/k/v
//         target + bias, written as [B,NH,S,HD] fp16.
// ---------------------------------------------------------------------------
#define GROW_B   144                 // bytes per smem row (72 halves)
#define GROW_W   36                  // words per smem row
#define GTILE_B  (128 * GROW_B)      // 18432 bytes per tile
#define GSTG_B   (2 * GTILE_B)       // A + B per stage (36864)
#define GEMM_SMEM (512 + 3 * GSTG_B) // bias + 3 stages = 111104

template <int MODE>
__global__ __launch_bounds__(256, 2) void gemm_f16(
    const __half* __restrict__ A, const __half* __restrict__ W,
    const float* __restrict__ b0, const float* __restrict__ b1,
    const float* __restrict__ b2, float* __restrict__ Cf,
    __half* __restrict__ o0, __half* __restrict__ o1, __half* __restrict__ o2,
    int Kdim)
{
    extern __shared__ char smc[];
    const uint32_t smem_base = smem_u32(smc);
    float* bias_s = (float*)smc;

    const int tid  = threadIdx.x;
    const int lane = tid & 31;
    const int warp = tid >> 5;
    const int wm   = (warp >> 1) * 32;   // 0,32,64,96
    const int wn   = (warp & 1) * 64;    // 0,64

    const int m0  = blockIdx.y * 128;
    const int n0g = blockIdx.x * 128;    // column across (possibly concat) W

    int nloc;
    int sel;
    const float* bias;
    if (MODE == 2) {
        sel  = n0g >> 11;                // 0:q 1:k 2:v
        nloc = n0g & 2047;
        bias = (sel == 0) ? b0 : (sel == 1) ? b1 : b2;
    } else {
        sel = 0; nloc = n0g; bias = b0;
    }
    if (tid < 128) bias_s[tid] = bias[nloc + tid];

    const int lrow = tid >> 1;           // 0..127
    const int lch0 = (tid & 1) * 4;      // 16B chunk base 0 or 4

    const __half* Ag = A + (size_t)(m0 + lrow) * Kdim;
    const __half* Wg = W + (size_t)(n0g + lrow) * Kdim;

    auto load_tile = [&](int stage, int k0 /*halves*/) {
        const uint32_t sa = smem_base + 512 + stage * GSTG_B + lrow * GROW_B;
        const uint32_t sb = sa + GTILE_B;
#pragma unroll
        for (int c = 0; c < 4; c++) {
            const int ch = lch0 + c;                 // 0..7
            cp_async16(sa + ch * 16, Ag + k0 + ch * 8);
            cp_async16(sb + ch * 16, Wg + k0 + ch * 8);
        }
        asm volatile("cp.async.commit_group;\n");
    };

    float acc[2][8][4];
#pragma unroll
    for (int i = 0; i < 2; i++)
#pragma unroll
        for (int j = 0; j < 8; j++)
#pragma unroll
            for (int t = 0; t < 4; t++) acc[i][j][t] = 0.0f;

    const int ntiles = Kdim / 64;        // >= 2 always here
    load_tile(0, 0);
    load_tile(1, 64);

    for (int kt = 0; kt < ntiles; kt++) {
        // Ensure load kt complete (kt+1 may stay in flight)
        if (kt + 1 < ntiles) asm volatile("cp.async.wait_group 1;\n");
        else                 asm volatile("cp.async.wait_group 0;\n");
        __syncthreads();   // all warps done computing tile kt-1 as well

        // Prefetch tile kt+2 into stage (kt+2)%3 == (kt-1)%3 (readers done)
        if (kt + 2 < ntiles) load_tile((kt + 2) % 3, (kt + 2) * 64);

        const uint32_t* As = (const uint32_t*)(smc + 512 + (kt % 3) * GSTG_B);
        const uint32_t* Bs = As + GTILE_B / 4;

#pragma unroll
        for (int ks = 0; ks < 4; ks++) {
            const int kk = ks * 8 + (lane & 3);
            uint32_t afr[2][4], bfr[8][2];
#pragma unroll
            for (int i = 0; i < 2; i++) {
                const int r = wm + i * 16 + (lane >> 2);
                afr[i][0] = As[r * GROW_W + kk];
                afr[i][1] = As[(r + 8) * GROW_W + kk];
                afr[i][2] = As[r * GROW_W + kk + 4];
                afr[i][3] = As[(r + 8) * GROW_W + kk + 4];
            }
#pragma unroll
            for (int j = 0; j < 8; j++) {
                const int n = wn + j * 8 + (lane >> 2);
                bfr[j][0] = Bs[n * GROW_W + kk];
                bfr[j][1] = Bs[n * GROW_W + kk + 4];
            }
#pragma unroll
            for (int i = 0; i < 2; i++)
#pragma unroll
                for (int j = 0; j < 8; j++)
                    mma_f16(acc[i][j], afr[i], bfr[j]);
        }
    }

    // Epilogue
    __half* Ch = (MODE == 2) ? ((sel == 0) ? o0 : (sel == 1) ? o1 : o2) : (__half*)0;
#pragma unroll
    for (int i = 0; i < 2; i++) {
        const int r = wm + i * 16 + (lane >> 2);
#pragma unroll
        for (int j = 0; j < 8; j++) {
            const int cc = wn + j * 8 + (lane & 3) * 2;
#pragma unroll
            for (int hh = 0; hh < 2; hh++) {
                const int m = m0 + r + hh * 8;
                const float v0 = acc[i][j][hh * 2 + 0] + bias_s[cc];
                const float v1 = acc[i][j][hh * 2 + 1] + bias_s[cc + 1];
                if (MODE == 0) {
                    *(float2*)(Cf + (size_t)m * HH + nloc + cc) = make_float2(v0, v1);
                } else {
                    const int b = m / SS, s = m % SS;
                    const int n = nloc + cc;
                    const int h = n >> 7, d = n & 127;   // HD = 128
                    __half2* dst = (__half2*)(Ch +
                        (((size_t)(b * NHH + h)) * SS + s) * HDD + d);
                    *dst = __floats2half2_rn(v0, v1);
                }
            }
        }
    }
}

// ---------------------------------------------------------------------------
// fp16 tensor-core flash attention (proven compute, cp.async double-buffered
// K/V loads — FIXED: full 16 chunks per 256-byte row, K and V per slot).
// Grid: (S/64, NH, B), 256 threads = 8 warps.
// S tile 64x64 (warps 4m x 2n, warp 16x32), O tile 64x128 (warp 16x64).
// Q/K/V smem rows padded to 136 halves (68 words); P rows to 72 halves.
// P.V uses ldmatrix.x4.trans on row-major V for B fragments.
// ---------------------------------------------------------------------------
#define FQ_ROW_H 136                  // halves per Q/K/V smem row
#define FQ_ROW_W 68
#define FQ_ROW_B 272
#define FP_ROW_H 72                   // halves per P smem row
#define FP_ROW_W 36
#define OFF_QS   0                    // 64*272 = 17408
#define KV_STG_B 34816                // K tile + V tile per stage
#define OFF_K0   17408                // K(s) = OFF_K0 + s*KV_STG_B
#define OFF_V0   34816                // V(s) = OFF_V0 + s*KV_STG_B
#define OFF_PS   87040                // 64*72*2 = 9216
#define OFF_MS   96256
#define OFF_LS   96512
#define OFF_CS   96768
#define OFF_RED  97024                // 128 floats
#define FLASH_SMEM 97536

__global__ __launch_bounds__(256) void flash_attn_f16(
    const __half* __restrict__ Q, const __half* __restrict__ K,
    const __half* __restrict__ V, __half* __restrict__ Out)
{
    extern __shared__ char smc[];
    const uint32_t smem_base = smem_u32(smc);
    __half* Qs = (__half*)(smc + OFF_QS);
    __half* Ps = (__half*)(smc + OFF_PS);
    float* m_s    = (float*)(smc + OFF_MS);
    float* l_s    = (float*)(smc + OFF_LS);
    float* corr_s = (float*)(smc + OFF_CS);
    float* red    = (float*)(smc + OFF_RED);
    const uint32_t* Qs32 = (const uint32_t*)Qs;
    const uint32_t* Ps32 = (const uint32_t*)Ps;

    const int tid  = threadIdx.x;
    const int lane = tid & 31;
    const int warp = tid >> 5;
    const int wmS  = (warp >> 1) * 16;
    const int wnS  = (warp & 1) * 32;
    const int wnO  = (warp & 1) * 64;
    const int wpn  = warp & 1;

    const int qb = blockIdx.x;
    const int h  = blockIdx.y;
    const int b  = blockIdx.z;
    const int q0 = qb * 64;

    const size_t head_base = ((size_t)(b * NHH + h)) * SS * HDD;
    const __half* Qg = Q + head_base + (size_t)q0 * HDD;
    const __half* Kg = K + head_base;
    const __half* Vg = V + head_base;

    const float qscale = 0.08838834764831845f;  // 1/sqrt(128)

    if (tid < 64) { m_s[tid] = -1e30f; l_s[tid] = 0.0f; }

    // Load Q tile: 64 rows x 128 halves = 1024 16B chunks (sync stores)
#pragma unroll
    for (int t = 0; t < 4; t++) {
        const int c = tid + t * 256;
        const int r = c >> 4, col = (c & 15) * 8;
        *(uint4*)&Qs[r * FQ_ROW_H + col] = *(const uint4*)(Qg + (size_t)r * HDD + col);
    }

    // Async K/V tile load: 1024 chunk-slots, each loads one K AND one V chunk.
    // r = slot>>4 (0..63 rows), ch = slot&15 (16 x 16B = full 256B row).
    auto load_kv = [&](int stage, int kb) {
        const int k0 = kb * 64;
        const uint32_t kbase = smem_base + OFF_K0 + stage * KV_STG_B;
        const uint32_t vbase = smem_base + OFF_V0 + stage * KV_STG_B;
#pragma unroll
        for (int t = 0; t < 4; t++) {
            const int idx = tid + t * 256;      // 0..1023
            const int r = idx >> 4, ch = idx & 15;
            cp_async16(kbase + r * FQ_ROW_B + ch * 16,
                       Kg + (size_t)(k0 + r) * HDD + ch * 8);
            cp_async16(vbase + r * FQ_ROW_B + ch * 16,
                       Vg + (size_t)(k0 + r) * HDD + ch * 8);
        }
        asm volatile("cp.async.commit_group;\n");
    };

    float o[8][4];
#pragma unroll
    for (int j = 0; j < 8; j++)
#pragma unroll
        for (int t = 0; t < 4; t++) o[j][t] = 0.0f;

    const int r0S = wmS + (lane >> 2);
    const int r1S = r0S + 8;

    // ldmatrix per-lane address pieces for V (rows = seq k, cols = head dim)
    const uint32_t v_lane_byte = (uint32_t)((lane & 15) * FQ_ROW_B + 16 * (lane >> 4));

    load_kv(0, 0);

    for (int kb = 0; kb <= qb; kb++) {
        const int s  = kb & 1;
        const int k0 = kb * 64;

        asm volatile("cp.async.wait_group 0;\n");
        __syncthreads();                 // K/V(s)+Q visible; prev compute done

        if (kb < qb) load_kv(s ^ 1, kb + 1);   // prefetch next block

        const uint32_t* Ks32 = (const uint32_t*)(smc + OFF_K0 + s * KV_STG_B);
        const uint32_t  voff = (uint32_t)(OFF_V0 + s * KV_STG_B);

        // ---- S = Q @ K^T (64x64x128), fp16 m16n8k16 ----
        float sv[4][4];
#pragma unroll
        for (int j = 0; j < 4; j++)
#pragma unroll
            for (int t = 0; t < 4; t++) sv[j][t] = 0.0f;

#pragma unroll
        for (int ks = 0; ks < 8; ks++) {
            const int kk = ks * 8 + (lane & 3);
            uint32_t a[4];
            a[0] = Qs32[r0S * FQ_ROW_W + kk];
            a[1] = Qs32[r1S * FQ_ROW_W + kk];
            a[2] = Qs32[r0S * FQ_ROW_W + kk + 4];
            a[3] = Qs32[r1S * FQ_ROW_W + kk + 4];
#pragma unroll
            for (int j = 0; j < 4; j++) {
                const int n = wnS + j * 8 + (lane >> 2);
                uint32_t bb[2];
                bb[0] = Ks32[n * FQ_ROW_W + kk];
                bb[1] = Ks32[n * FQ_ROW_W + kk + 4];
                mma_f16(sv[j], a, bb);
            }
        }

#pragma unroll
        for (int j = 0; j < 4; j++)
#pragma unroll
            for (int t = 0; t < 4; t++) sv[j][t] *= qscale;

        if (kb == qb) {
#pragma unroll
            for (int j = 0; j < 4; j++) {
                const int cg = k0 + wnS + j * 8 + (lane & 3) * 2;
#pragma unroll
                for (int t = 0; t < 4; t++) {
                    const int rg = q0 + ((t < 2) ? r0S : r1S);
                    if (cg + (t & 1) > rg) sv[j][t] = -1e30f;
                }
            }
        }

        // partial row max across this warp's 32 cols
        float mx0 = -1e30f, mx1 = -1e30f;
#pragma unroll
        for (int j = 0; j < 4; j++) {
            mx0 = fmaxf(mx0, fmaxf(sv[j][0], sv[j][1]));
            mx1 = fmaxf(mx1, fmaxf(sv[j][2], sv[j][3]));
        }
        mx0 = fmaxf(mx0, __shfl_xor_sync(0xffffffffu, mx0, 1));
        mx0 = fmaxf(mx0, __shfl_xor_sync(0xffffffffu, mx0, 2));
        mx1 = fmaxf(mx1, __shfl_xor_sync(0xffffffffu, mx1, 1));
        mx1 = fmaxf(mx1, __shfl_xor_sync(0xffffffffu, mx1, 2));
        if ((lane & 3) == 0) {
            red[r0S + 64 * wpn] = mx0;
            red[r1S + 64 * wpn] = mx1;
        }
        __syncthreads();

        if (tid < 64) {
            const float m_old = m_s[tid];
            const float m_new = fmaxf(m_old, fmaxf(red[tid], red[tid + 64]));
            m_s[tid]    = m_new;
            corr_s[tid] = __expf(m_old - m_new);
        }
        __syncthreads();

        // exp, P -> smem fp16, partial row sums
        {
            const float mn0 = m_s[r0S];
            const float mn1 = m_s[r1S];
            float sum0 = 0.0f, sum1 = 0.0f;
#pragma unroll
            for (int j = 0; j < 4; j++) {
                const int colw = (wnS >> 1) + j * 4 + (lane & 3);  // half2 word idx
                float p0 = __expf(sv[j][0] - mn0);
                float p1 = __expf(sv[j][1] - mn0);
                float p2 = __expf(sv[j][2] - mn1);
                float p3 = __expf(sv[j][3] - mn1);
                sum0 += p0 + p1; sum1 += p2 + p3;
                ((__half2*)Ps)[r0S * FP_ROW_W + colw] = __floats2half2_rn(p0, p1);
                ((__half2*)Ps)[r1S * FP_ROW_W + colw] = __floats2half2_rn(p2, p3);
            }
            sum0 += __shfl_xor_sync(0xffffffffu, sum0, 1);
            sum0 += __shfl_xor_sync(0xffffffffu, sum0, 2);
            sum1 += __shfl_xor_sync(0xffffffffu, sum1, 1);
            sum1 += __shfl_xor_sync(0xffffffffu, sum1, 2);
            if ((lane & 3) == 0) {
                red[r0S + 64 * wpn] = sum0;
                red[r1S + 64 * wpn] = sum1;
            }
        }
        __syncthreads();

        if (tid < 64)
            l_s[tid] = l_s[tid] * corr_s[tid] + red[tid] + red[tid + 64];

        // ---- O = corr*O + P @ V  (64x128x64), V via ldmatrix.trans ----
        {
            const float c0 = corr_s[r0S];
            const float c1 = corr_s[r1S];
#pragma unroll
            for (int j = 0; j < 8; j++) {
                o[j][0] *= c0; o[j][1] *= c0;
                o[j][2] *= c1; o[j][3] *= c1;
            }
#pragma unroll
            for (int ks = 0; ks < 4; ks++) {
                const int kk = ks * 8 + (lane & 3);
                uint32_t a[4];
                a[0] = Ps32[r0S * FP_ROW_W + kk];
                a[1] = Ps32[r1S * FP_ROW_W + kk];
                a[2] = Ps32[r0S * FP_ROW_W + kk + 4];
                a[3] = Ps32[r1S * FP_ROW_W + kk + 4];
#pragma unroll
                for (int jj = 0; jj < 4; jj++) {
                    uint32_t b0, b1, b2, b3;
                    const uint32_t vaddr = smem_base + voff +
                        (uint32_t)(ks * 16) * FQ_ROW_B +
                        (uint32_t)((wnO + jj * 16) * 2) + v_lane_byte;
                    ldmatrix_x4_trans(b0, b1, b2, b3, vaddr);
                    uint32_t bb0[2] = {b0, b1};
                    uint32_t bb1[2] = {b2, b3};
                    mma_f16(o[jj * 2 + 0], a, bb0);
                    mma_f16(o[jj * 2 + 1], a, bb1);
                }
            }
        }
        __syncthreads();
    }

    // epilogue: normalize, write att [B,S,H] fp16
    {
        const float inv0 = 1.0f / l_s[r0S];
        const float inv1 = 1.0f / l_s[r1S];
        __half* dst0 = Out + ((size_t)(b * SS + q0 + r0S)) * HH + h * HDD;
        __half* dst1 = Out + ((size_t)(b * SS + q0 + r1S)) * HH + h * HDD;
#pragma unroll
        for (int j = 0; j < 8; j++) {
            const int col = wnO + j * 8 + (lane & 3) * 2;
            *(__half2*)(dst0 + col) = __floats2half2_rn(o[j][0] * inv0, o[j][1] * inv0);
            *(__half2*)(dst1 + col) = __floats2half2_rn(o[j][2] * inv1, o[j][3] * inv1);
        }
    }
}

// ---------------------------------------------------------------------------
// Launch
// ---------------------------------------------------------------------------
extern "C" void kernel_launch(void* const* d_in, const int* in_sizes, int n_in,
                              void* d_out, int out_size)
{
    const float* hidden = (const float*)d_in[0];
    // d_in[1] = causal_mask: handled analytically
    const float* Wq = (const float*)d_in[2];
    const float* bq = (const float*)d_in[3];
    const float* Wk = (const float*)d_in[4];
    const float* bk = (const float*)d_in[5];
    const float* Wv = (const float*)d_in[6];
    const float* bv = (const float*)d_in[7];
    const float* Wo = (const float*)d_in[8];
    const float* bo = (const float*)d_in[9];
    float* out = (float*)d_out;

    __half *q, *k, *v, *att, *hidt, *wt, *wo;
    cudaGetSymbolAddress((void**)&q,    g_q);
    cudaGetSymbolAddress((void**)&k,    g_k);
    cudaGetSymbolAddress((void**)&v,    g_v);
    cudaGetSymbolAddress((void**)&att,  g_att);
    cudaGetSymbolAddress((void**)&hidt, g_hidt);
    cudaGetSymbolAddress((void**)&wt,   g_wt);
    cudaGetSymbolAddress((void**)&wo,   g_wo);

    // Convert inputs to fp16 (QKV weights into concat layout for fused GEMM)
    const int HN4 = MM * HH / 4;
    const int WN4 = HH * HH / 4;
    cvt_f2h<<<HN4 / 256, 256>>>(hidden, hidt, HN4);
    cvt_f2h<<<WN4 / 256, 256>>>(Wq, wt + 0 * (size_t)HH * HH, WN4);
    cvt_f2h<<<WN4 / 256, 256>>>(Wk, wt + 1 * (size_t)HH * HH, WN4);
    cvt_f2h<<<WN4 / 256, 256>>>(Wv, wt + 2 * (size_t)HH * HH, WN4);
    cvt_f2h<<<WN4 / 256, 256>>>(Wo, wo, WN4);

    cudaFuncSetAttribute(gemm_f16<0>, cudaFuncAttributeMaxDynamicSharedMemorySize,
                         GEMM_SMEM);
    cudaFuncSetAttribute(gemm_f16<2>, cudaFuncAttributeMaxDynamicSharedMemorySize,
                         GEMM_SMEM);
    cudaFuncSetAttribute(flash_attn_f16, cudaFuncAttributeMaxDynamicSharedMemorySize,
                         FLASH_SMEM);

    // Fused QKV projection: N = 6144 over concatenated weights (1536 CTAs)
    gemm_f16<2><<<dim3(48, MM / 128), 256, GEMM_SMEM>>>(
        hidt, wt, bq, bk, bv, nullptr, q, k, v, HH);

    // Flash attention (proven compute, double-buffered loads — fixed)
    flash_attn_f16<<<dim3(SS / 64, NHH, BB), 256, FLASH_SMEM>>>(q, k, v, att);

    // Output projection (fp32 result)
    gemm_f16<0><<<dim3(16, MM / 128), 256, GEMM_SMEM>>>(
        att, wo, bo, nullptr, nullptr, out, nullptr, nullptr, nullptr, HH);
}

// round 15
// speedup vs baseline: 6.3870x; 1.0480x over previous
#include <cuda_runtime.h>
#include <cuda_fp16.h>
#include <cstdint>
#include <cstddef>

// Problem constants (fixed by the reference)
#define BB   2
#define SS   2048
#define HH   2048
#define NHH  16
#define HDD  128
#define MM   (BB * SS)   // 4096 rows

// ---------------------------------------------------------------------------
// Scratch (allocation-free rule: __device__ globals)
// ---------------------------------------------------------------------------
__device__ __half g_q[(size_t)BB * NHH * SS * HDD];   // [B,NH,S,HD]
__device__ __half g_k[(size_t)BB * NHH * SS * HDD];
__device__ __half g_v[(size_t)BB * NHH * SS * HDD];
__device__ __half g_att[(size_t)MM * HH];             // [B,S,H]
__device__ __half g_hidt[(size_t)MM * HH];            // hidden, fp16
__device__ __half g_wt[(size_t)3 * HH * HH];          // Wq,Wk,Wv concat (fp16)
__device__ __half g_wo[(size_t)HH * HH];              // Wo fp16

// ---------------------------------------------------------------------------
// Helpers
// ---------------------------------------------------------------------------
__device__ __forceinline__ void mma_f16(float c[4], const uint32_t a[4],
                                        const uint32_t b[2]) {
    asm volatile(
        "mma.sync.aligned.m16n8k16.row.col.f32.f16.f16.f32 "
        "{%0,%1,%2,%3}, {%4,%5,%6,%7}, {%8,%9}, {%0,%1,%2,%3};\n"
        : "+f"(c[0]), "+f"(c[1]), "+f"(c[2]), "+f"(c[3])
        : "r"(a[0]), "r"(a[1]), "r"(a[2]), "r"(a[3]), "r"(b[0]), "r"(b[1]));
}

__device__ __forceinline__ void cp_async16(uint32_t s, const void* g) {
    asm volatile("cp.async.cg.shared.global [%0], [%1], 16;\n" :: "r"(s), "l"(g));
}

__device__ __forceinline__ uint32_t smem_u32(const void* p) {
    return (uint32_t)__cvta_generic_to_shared(p);
}

__device__ __forceinline__ void ldmx4(uint32_t& r0, uint32_t& r1,
                                      uint32_t& r2, uint32_t& r3, uint32_t a) {
    asm volatile(
        "ldmatrix.sync.aligned.m8n8.x4.shared.b16 {%0,%1,%2,%3}, [%4];"
        : "=r"(r0), "=r"(r1), "=r"(r2), "=r"(r3) : "r"(a));
}

__device__ __forceinline__ void ldmx4t(uint32_t& r0, uint32_t& r1,
                                       uint32_t& r2, uint32_t& r3, uint32_t a) {
    asm volatile(
        "ldmatrix.sync.aligned.m8n8.x4.trans.shared.b16 {%0,%1,%2,%3}, [%4];"
        : "=r"(r0), "=r"(r1), "=r"(r2), "=r"(r3) : "r"(a));
}

__device__ __forceinline__ uint32_t packh2(float a, float b) {
    __half2 h = __floats2half2_rn(a, b);
    return *(uint32_t*)&h;
}

// ---------------------------------------------------------------------------
// Pre-convert: fp32 -> fp16 (rn), vectorized
// ---------------------------------------------------------------------------
__global__ __launch_bounds__(256) void cvt_f2h(const float* __restrict__ in,
                                               __half* __restrict__ out, int n4)
{
    int i = blockIdx.x * 256 + threadIdx.x;
    if (i < n4) {
        float4 v = ((const float4*)in)[i];
        __half2* o = (__half2*)(out + (size_t)i * 4);
        o[0] = __floats2half2_rn(v.x, v.y);
        o[1] = __floats2half2_rn(v.z, v.w);
    }
}

// ---------------------------------------------------------------------------
// fp16 tensor-core GEMM: C = A @ W^T + bias.  (proven R14 body, unchanged)
// Block 128x128, BK=64 halves, THREE-stage cp.async pipeline, ONE sync/tile.
// 8 warps, warp tile 32x64. Smem rows padded to 72 halves -> conflict-free.
// MODE 0: single fp32 row-major output (final projection).
// MODE 2: fused QKV — W has 3*HH concat rows; block column selects q/k/v
//         target + bias, written as [B,NH,S,HD] fp16.
// ---------------------------------------------------------------------------
#define GROW_B   144                 // bytes per smem row (72 halves)
#define GROW_W   36                  // words per smem row
#define GTILE_B  (128 * GROW_B)      // 18432 bytes per tile
#define GSTG_B   (2 * GTILE_B)       // A + B per stage (36864)
#define GEMM_SMEM (512 + 3 * GSTG_B) // bias + 3 stages = 111104

template <int MODE>
__global__ __launch_bounds__(256, 2) void gemm_f16(
    const __half* __restrict__ A, const __half* __restrict__ W,
    const float* __restrict__ b0, const float* __restrict__ b1,
    const float* __restrict__ b2, float* __restrict__ Cf,
    __half* __restrict__ o0, __half* __restrict__ o1, __half* __restrict__ o2,
    int Kdim)
{
    extern __shared__ char smc[];
    const uint32_t smem_base = smem_u32(smc);
    float* bias_s = (float*)smc;

    const int tid  = threadIdx.x;
    const int lane = tid & 31;
    const int warp = tid >> 5;
    const int wm   = (warp >> 1) * 32;   // 0,32,64,96
    const int wn   = (warp & 1) * 64;    // 0,64

    const int m0  = blockIdx.y * 128;
    const int n0g = blockIdx.x * 128;    // column across (possibly concat) W

    int nloc;
    int sel;
    const float* bias;
    if (MODE == 2) {
        sel  = n0g >> 11;                // 0:q 1:k 2:v
        nloc = n0g & 2047;
        bias = (sel == 0) ? b0 : (sel == 1) ? b1 : b2;
    } else {
        sel = 0; nloc = n0g; bias = b0;
    }
    if (tid < 128) bias_s[tid] = bias[nloc + tid];

    const int lrow = tid >> 1;           // 0..127
    const int lch0 = (tid & 1) * 4;      // 16B chunk base 0 or 4

    const __half* Ag = A + (size_t)(m0 + lrow) * Kdim;
    const __half* Wg = W + (size_t)(n0g + lrow) * Kdim;

    auto load_tile = [&](int stage, int k0 /*halves*/) {
        const uint32_t sa = smem_base + 512 + stage * GSTG_B + lrow * GROW_B;
        const uint32_t sb = sa + GTILE_B;
#pragma unroll
        for (int c = 0; c < 4; c++) {
            const int ch = lch0 + c;                 // 0..7
            cp_async16(sa + ch * 16, Ag + k0 + ch * 8);
            cp_async16(sb + ch * 16, Wg + k0 + ch * 8);
        }
        asm volatile("cp.async.commit_group;\n");
    };

    float acc[2][8][4];
#pragma unroll
    for (int i = 0; i < 2; i++)
#pragma unroll
        for (int j = 0; j < 8; j++)
#pragma unroll
            for (int t = 0; t < 4; t++) acc[i][j][t] = 0.0f;

    const int ntiles = Kdim / 64;        // >= 2 always here
    load_tile(0, 0);
    load_tile(1, 64);

    for (int kt = 0; kt < ntiles; kt++) {
        // Ensure load kt complete (kt+1 may stay in flight)
        if (kt + 1 < ntiles) asm volatile("cp.async.wait_group 1;\n");
        else                 asm volatile("cp.async.wait_group 0;\n");
        __syncthreads();   // all warps done computing tile kt-1 as well

        // Prefetch tile kt+2 into stage (kt+2)%3 == (kt-1)%3 (readers done)
        if (kt + 2 < ntiles) load_tile((kt + 2) % 3, (kt + 2) * 64);

        const uint32_t* As = (const uint32_t*)(smc + 512 + (kt % 3) * GSTG_B);
        const uint32_t* Bs = As + GTILE_B / 4;

#pragma unroll
        for (int ks = 0; ks < 4; ks++) {
            const int kk = ks * 8 + (lane & 3);
            uint32_t afr[2][4], bfr[8][2];
#pragma unroll
            for (int i = 0; i < 2; i++) {
                const int r = wm + i * 16 + (lane >> 2);
                afr[i][0] = As[r * GROW_W + kk];
                afr[i][1] = As[(r + 8) * GROW_W + kk];
                afr[i][2] = As[r * GROW_W + kk + 4];
                afr[i][3] = As[(r + 8) * GROW_W + kk + 4];
            }
#pragma unroll
            for (int j = 0; j < 8; j++) {
                const int n = wn + j * 8 + (lane >> 2);
                bfr[j][0] = Bs[n * GROW_W + kk];
                bfr[j][1] = Bs[n * GROW_W + kk + 4];
            }
#pragma unroll
            for (int i = 0; i < 2; i++)
#pragma unroll
                for (int j = 0; j < 8; j++)
                    mma_f16(acc[i][j], afr[i], bfr[j]);
        }
    }

    // Epilogue
    __half* Ch = (MODE == 2) ? ((sel == 0) ? o0 : (sel == 1) ? o1 : o2) : (__half*)0;
#pragma unroll
    for (int i = 0; i < 2; i++) {
        const int r = wm + i * 16 + (lane >> 2);
#pragma unroll
        for (int j = 0; j < 8; j++) {
            const int cc = wn + j * 8 + (lane & 3) * 2;
#pragma unroll
            for (int hh = 0; hh < 2; hh++) {
                const int m = m0 + r + hh * 8;
                const float v0 = acc[i][j][hh * 2 + 0] + bias_s[cc];
                const float v1 = acc[i][j][hh * 2 + 1] + bias_s[cc + 1];
                if (MODE == 0) {
                    *(float2*)(Cf + (size_t)m * HH + nloc + cc) = make_float2(v0, v1);
                } else {
                    const int b = m / SS, s = m % SS;
                    const int n = nloc + cc;
                    const int h = n >> 7, d = n & 127;   // HD = 128
                    __half2* dst = (__half2*)(Ch +
                        (((size_t)(b * NHH + h)) * SS + s) * HDD + d);
                    *dst = __floats2half2_rn(v0, v1);
                }
            }
        }
    }
}

// ---------------------------------------------------------------------------
// FA2-style fp16 flash attention: 128 q-rows per CTA, warp owns 16 rows.
// Softmax entirely in registers (quad shuffles), S frags repacked as P·V
// A-frags (no P smem), one __syncthreads per k-block, cp.async K/V double
// buffering, warp-level causal early-out.
// FIXED loads: every 256-byte row = 16 x 16B chunks (Q: 2048 slots; K/V:
// 1024 slots x {K,V}).
// Grid: (16, NH, B); 256 threads = 8 warps.
// ---------------------------------------------------------------------------
#define FROW_B   272                  // bytes per smem row (136 halves)
#define FOFF_Q   0                    // 128 * 272 = 34816
#define FOFF_K   34816                // + s*17408
#define FOFF_V   69632                // + s*17408
#define FLASH_SMEM 104448

__global__ __launch_bounds__(256, 1) void flash_attn_f16(
    const __half* __restrict__ Q, const __half* __restrict__ K,
    const __half* __restrict__ V, __half* __restrict__ Out)
{
    extern __shared__ char smc[];
    const uint32_t sb = smem_u32(smc);

    const int tid  = threadIdx.x;
    const int lane = tid & 31;
    const int warp = tid >> 5;

    const int qi = 15 - blockIdx.x;      // longest CTAs launch first
    const int h  = blockIdx.y;
    const int b  = blockIdx.z;
    const int q0 = qi * 128;

    const size_t head_base = ((size_t)(b * NHH + h)) * SS * HDD;
    const __half* Qg = Q + head_base + (size_t)q0 * HDD;
    const __half* Kg = K + head_base;
    const __half* Vg = V + head_base;

    const float qscale = 0.08838834764831845f;  // 1/sqrt(128)

    // ---- stage Q (128 rows x 256 B = 2048 16B chunks) ----
#pragma unroll
    for (int t = 0; t < 8; t++) {
        const int idx = tid + t * 256;        // 0..2047
        const int r = idx >> 4, ch = idx & 15;
        *(uint4*)(smc + FOFF_Q + r * FROW_B + ch * 16) =
            *(const uint4*)(Qg + (size_t)r * HDD + ch * 8);
    }
    __syncthreads();

    const uint32_t lm_row = (uint32_t)(lane & 15);
    const uint32_t lm_chb = (uint32_t)((lane >> 4) * 16);

    uint32_t qf[8][4];
    {
        const uint32_t qbase = sb + FOFF_Q + (warp * 16 + lm_row) * FROW_B + lm_chb;
#pragma unroll
        for (int kc = 0; kc < 8; kc++)
            ldmx4(qf[kc][0], qf[kc][1], qf[kc][2], qf[kc][3], qbase + kc * 32);
    }

    float o[16][4];
#pragma unroll
    for (int j = 0; j < 16; j++)
#pragma unroll
        for (int t = 0; t < 4; t++) o[j][t] = 0.0f;
    float m0 = -1e30f, m1 = -1e30f, l0 = 0.0f, l1 = 0.0f;

    const int nkb = 2 * (qi + 1);
    const int wr0 = q0 + warp * 16;           // warp's min global q row
    const int rg0 = wr0 + (lane >> 2);        // this thread's rows
    const int rg1 = rg0 + 8;

    // FIXED: 1024 slots, each loads one K chunk AND one V chunk (full rows)
    auto load_kv = [&](int stage, int kb) {
        const int k0 = kb * 64;
        const uint32_t kbase = sb + FOFF_K + stage * 17408;
        const uint32_t vbase = sb + FOFF_V + stage * 17408;
#pragma unroll
        for (int t = 0; t < 4; t++) {
            const int idx = tid + t * 256;    // 0..1023
            const int r = idx >> 4, ch = idx & 15;
            cp_async16(kbase + r * FROW_B + ch * 16,
                       Kg + (size_t)(k0 + r) * HDD + ch * 8);
            cp_async16(vbase + r * FROW_B + ch * 16,
                       Vg + (size_t)(k0 + r) * HDD + ch * 8);
        }
        asm volatile("cp.async.commit_group;\n");
    };

    load_kv(0, 0);

    for (int kb = 0; kb < nkb; kb++) {
        const int s  = kb & 1;
        const int k0 = kb * 64;

        asm volatile("cp.async.wait_group 0;\n");
        __syncthreads();                       // load done + prev compute done
        if (kb + 1 < nkb) load_kv(s ^ 1, kb + 1);

        if (k0 <= wr0 + 15) {                  // not fully above diagonal
            // ---- S = Q @ K^T (16 x 64 per warp) ----
            float sv[8][4];
#pragma unroll
            for (int j = 0; j < 8; j++)
#pragma unroll
                for (int t = 0; t < 4; t++) sv[j][t] = 0.0f;

            const uint32_t kbase = sb + FOFF_K + s * 17408 + lm_row * FROW_B + lm_chb;
#pragma unroll
            for (int kc = 0; kc < 8; kc++) {
#pragma unroll
                for (int np = 0; np < 4; np++) {
                    uint32_t r0, r1, r2, r3;
                    ldmx4(r0, r1, r2, r3, kbase + np * 16 * FROW_B + kc * 32);
                    uint32_t bb0[2] = {r0, r2};
                    uint32_t bb1[2] = {r1, r3};
                    mma_f16(sv[2 * np],     qf[kc], bb0);
                    mma_f16(sv[2 * np + 1], qf[kc], bb1);
                }
            }

            // scale + causal mask
#pragma unroll
            for (int j = 0; j < 8; j++)
#pragma unroll
                for (int t = 0; t < 4; t++) sv[j][t] *= qscale;

            if (k0 + 63 > wr0) {
#pragma unroll
                for (int j = 0; j < 8; j++) {
                    const int cg = k0 + j * 8 + (lane & 3) * 2;
                    if (cg     > rg0) sv[j][0] = -1e30f;
                    if (cg + 1 > rg0) sv[j][1] = -1e30f;
                    if (cg     > rg1) sv[j][2] = -1e30f;
                    if (cg + 1 > rg1) sv[j][3] = -1e30f;
                }
            }

            // ---- online softmax in registers (quad reduction) ----
            float mx0 = -1e30f, mx1 = -1e30f;
#pragma unroll
            for (int j = 0; j < 8; j++) {
                mx0 = fmaxf(mx0, fmaxf(sv[j][0], sv[j][1]));
                mx1 = fmaxf(mx1, fmaxf(sv[j][2], sv[j][3]));
            }
            mx0 = fmaxf(mx0, __shfl_xor_sync(0xffffffffu, mx0, 1));
            mx0 = fmaxf(mx0, __shfl_xor_sync(0xffffffffu, mx0, 2));
            mx1 = fmaxf(mx1, __shfl_xor_sync(0xffffffffu, mx1, 1));
            mx1 = fmaxf(mx1, __shfl_xor_sync(0xffffffffu, mx1, 2));

            const float mn0 = fmaxf(m0, mx0);
            const float mn1 = fmaxf(m1, mx1);
            const float corr0 = __expf(m0 - mn0);
            const float corr1 = __expf(m1 - mn1);
            m0 = mn0; m1 = mn1;

            float sum0 = 0.0f, sum1 = 0.0f;
#pragma unroll
            for (int j = 0; j < 8; j++) {
                sv[j][0] = __expf(sv[j][0] - mn0);
                sv[j][1] = __expf(sv[j][1] - mn0);
                sv[j][2] = __expf(sv[j][2] - mn1);
                sv[j][3] = __expf(sv[j][3] - mn1);
                sum0 += sv[j][0] + sv[j][1];
                sum1 += sv[j][2] + sv[j][3];
            }
            sum0 += __shfl_xor_sync(0xffffffffu, sum0, 1);
            sum0 += __shfl_xor_sync(0xffffffffu, sum0, 2);
            sum1 += __shfl_xor_sync(0xffffffffu, sum1, 1);
            sum1 += __shfl_xor_sync(0xffffffffu, sum1, 2);
            l0 = l0 * corr0 + sum0;
            l1 = l1 * corr1 + sum1;

#pragma unroll
            for (int j = 0; j < 16; j++) {
                o[j][0] *= corr0; o[j][1] *= corr0;
                o[j][2] *= corr1; o[j][3] *= corr1;
            }

            // ---- O += P @ V ;  P a-frags packed straight from sv ----
            const uint32_t vbase = sb + FOFF_V + s * 17408 + lm_row * FROW_B + lm_chb;
#pragma unroll
            for (int t = 0; t < 4; t++) {
                uint32_t pa[4];
                pa[0] = packh2(sv[2 * t][0],     sv[2 * t][1]);
                pa[1] = packh2(sv[2 * t][2],     sv[2 * t][3]);
                pa[2] = packh2(sv[2 * t + 1][0], sv[2 * t + 1][1]);
                pa[3] = packh2(sv[2 * t + 1][2], sv[2 * t + 1][3]);
                const uint32_t vrow = vbase + t * 16 * FROW_B;
#pragma unroll
                for (int nj = 0; nj < 8; nj++) {
                    uint32_t r0, r1, r2, r3;
                    ldmx4t(r0, r1, r2, r3, vrow + nj * 32);
                    uint32_t bb0[2] = {r0, r1};
                    uint32_t bb1[2] = {r2, r3};
                    mma_f16(o[2 * nj],     pa, bb0);
                    mma_f16(o[2 * nj + 1], pa, bb1);
                }
            }
        }
    }

    // ---- epilogue: normalize, write att [B,S,H] fp16 ----
    {
        const float inv0 = 1.0f / l0;
        const float inv1 = 1.0f / l1;
        __half* dst0 = Out + ((size_t)(b * SS + rg0)) * HH + h * HDD;
        __half* dst1 = Out + ((size_t)(b * SS + rg1)) * HH + h * HDD;
#pragma unroll
        for (int j = 0; j < 16; j++) {
            const int col = j * 8 + (lane & 3) * 2;
            *(__half2*)(dst0 + col) = __floats2half2_rn(o[j][0] * inv0, o[j][1] * inv0);
            *(__half2*)(dst1 + col) = __floats2half2_rn(o[j][2] * inv1, o[j][3] * inv1);
        }
    }
}

// ---------------------------------------------------------------------------
// Launch
// ---------------------------------------------------------------------------
extern "C" void kernel_launch(void* const* d_in, const int* in_sizes, int n_in,
                              void* d_out, int out_size)
{
    const float* hidden = (const float*)d_in[0];
    // d_in[1] = causal_mask: handled analytically
    const float* Wq = (const float*)d_in[2];
    const float* bq = (const float*)d_in[3];
    const float* Wk = (const float*)d_in[4];
    const float* bk = (const float*)d_in[5];
    const float* Wv = (const float*)d_in[6];
    const float* bv = (const float*)d_in[7];
    const float* Wo = (const float*)d_in[8];
    const float* bo = (const float*)d_in[9];
    float* out = (float*)d_out;

    __half *q, *k, *v, *att, *hidt, *wt, *wo;
    cudaGetSymbolAddress((void**)&q,    g_q);
    cudaGetSymbolAddress((void**)&k,    g_k);
    cudaGetSymbolAddress((void**)&v,    g_v);
    cudaGetSymbolAddress((void**)&att,  g_att);
    cudaGetSymbolAddress((void**)&hidt, g_hidt);
    cudaGetSymbolAddress((void**)&wt,   g_wt);
    cudaGetSymbolAddress((void**)&wo,   g_wo);

    // Convert inputs to fp16 (QKV weights into concat layout for fused GEMM)
    const int HN4 = MM * HH / 4;
    const int WN4 = HH * HH / 4;
    cvt_f2h<<<HN4 / 256, 256>>>(hidden, hidt, HN4);
    cvt_f2h<<<WN4 / 256, 256>>>(Wq, wt + 0 * (size_t)HH * HH, WN4);
    cvt_f2h<<<WN4 / 256, 256>>>(Wk, wt + 1 * (size_t)HH * HH, WN4);
    cvt_f2h<<<WN4 / 256, 256>>>(Wv, wt + 2 * (size_t)HH * HH, WN4);
    cvt_f2h<<<WN4 / 256, 256>>>(Wo, wo, WN4);

    cudaFuncSetAttribute(gemm_f16<0>, cudaFuncAttributeMaxDynamicSharedMemorySize,
                         GEMM_SMEM);
    cudaFuncSetAttribute(gemm_f16<2>, cudaFuncAttributeMaxDynamicSharedMemorySize,
                         GEMM_SMEM);
    cudaFuncSetAttribute(flash_attn_f16, cudaFuncAttributeMaxDynamicSharedMemorySize,
                         FLASH_SMEM);

    // Fused QKV projection: N = 6144 over concatenated weights (1536 CTAs)
    gemm_f16<2><<<dim3(48, MM / 128), 256, GEMM_SMEM>>>(
        hidt, wt, bq, bk, bv, nullptr, q, k, v, HH);

    // FA2 flash attention (128 q-rows/CTA, register softmax, fixed loads)
    flash_attn_f16<<<dim3(16, NHH, BB), 256, FLASH_SMEM>>>(q, k, v, att);

    // Output projection (fp32 result)
    gemm_f16<0><<<dim3(16, MM / 128), 256, GEMM_SMEM>>>(
        att, wo, bo, nullptr, nullptr, out, nullptr, nullptr, nullptr, HH);
}